// round 8
// baseline (speedup 1.0000x reference)
#include <cuda_runtime.h>
#include <cuda_bf16.h>
#include <math.h>
#include <stdint.h>

#define HID 2048
#define TT 1024
#define NH 32
#define HD 64
#define INTER 5632

typedef __nv_bfloat16 bf16;

// ---------------- scratch (no allocations allowed) ----------------
__device__ float g_h[TT*HID];
__device__ float g_qr[TT*HID];
__device__ float g_kr[TT*HID];
__device__ float g_vr[TT*HID];
__device__ float g_q[TT*HID];
__device__ float g_k[TT*HID];
__device__ float g_v[TT*HID];
__device__ float g_beta[TT*NH];
__device__ float g_o[TT*HID];
__device__ float g_on[TT*HID];
__device__ float g_x1[TT*HID];
__device__ float g_h2[TT*HID];
__device__ float g_gate[TT*INTER];
__device__ float g_up[TT*INTER];
__device__ float g_Ssc[NH*HD*HD];

// bf16 split pairs (activations)
__device__ bf16 g_hh[TT*HID],  g_hl[TT*HID];
__device__ bf16 g_onh[TT*HID], g_onl[TT*HID];
__device__ bf16 g_h2h[TT*HID], g_h2l[TT*HID];
__device__ bf16 g_acth[TT*INTER], g_actl[TT*INTER];
// bf16 split pairs (weights)
__device__ bf16 g_wqh[HID*HID], g_wql[HID*HID];
__device__ bf16 g_wkh[HID*HID], g_wkl[HID*HID];
__device__ bf16 g_wvh[HID*HID], g_wvl[HID*HID];
__device__ bf16 g_woh[HID*HID], g_wol[HID*HID];
__device__ bf16 g_wgh[INTER*HID], g_wgl[INTER*HID];
__device__ bf16 g_wuh[INTER*HID], g_wul[INTER*HID];
__device__ bf16 g_wdh[HID*INTER], g_wdl[HID*INTER];

// ================= helpers =================
__device__ __forceinline__ uint32_t smem_u32(const void* p) {
    uint32_t a;
    asm("{ .reg .u64 t; cvta.to.shared.u64 t, %1; cvt.u32.u64 %0, t; }" : "=r"(a) : "l"(p));
    return a;
}
__device__ __forceinline__ void ldmx4(uint32_t& r0, uint32_t& r1, uint32_t& r2, uint32_t& r3,
                                      uint32_t addr) {
    asm volatile("ldmatrix.sync.aligned.m8n8.x4.shared.b16 {%0,%1,%2,%3}, [%4];"
                 : "=r"(r0), "=r"(r1), "=r"(r2), "=r"(r3) : "r"(addr));
}
__device__ __forceinline__ void mma16816(float* c, const uint32_t* a, const uint32_t* b) {
    asm volatile(
        "mma.sync.aligned.m16n8k16.row.col.f32.bf16.bf16.f32 "
        "{%0,%1,%2,%3}, {%4,%5,%6,%7}, {%8,%9}, {%0,%1,%2,%3};"
        : "+f"(c[0]), "+f"(c[1]), "+f"(c[2]), "+f"(c[3])
        : "r"(a[0]), "r"(a[1]), "r"(a[2]), "r"(a[3]), "r"(b[0]), "r"(b[1]));
}
__device__ __forceinline__ void cpasync16(uint32_t saddr, const void* gptr) {
    asm volatile("cp.async.ca.shared.global [%0], [%1], 16;" :: "r"(saddr), "l"(gptr));
}
#define CP_COMMIT() asm volatile("cp.async.commit_group;" ::: "memory")
__device__ __forceinline__ void cp_wait(int pend) {
    if (pend == 0)      asm volatile("cp.async.wait_group 0;" ::: "memory");
    else if (pend == 1) asm volatile("cp.async.wait_group 1;" ::: "memory");
    else                asm volatile("cp.async.wait_group 2;" ::: "memory");
}
__device__ __forceinline__ uint32_t pack_bf16x2(float a, float b) {
    __nv_bfloat162 r;
    r.x = __float2bfloat16_rn(a);
    r.y = __float2bfloat16_rn(b);
    return *(uint32_t*)&r;
}
__device__ __forceinline__ void split1(float x, bf16& h, bf16& l) {
    h = __float2bfloat16_rn(x);
    l = __float2bfloat16_rn(x - __bfloat162float(h));
}

// ================= bf16-split tensor GEMM =================
// C[M,N] = Ah@Bh^T + Ah@Bl^T + Al@Bh^T  (+Rsd).  128x128 tile, BK=64,
// 3-stage cp.async ring, one barrier per chunk. 8 warps (2x4), 64x32 warp tile.
#define BK 64
#define PADW 72                       // 144B row stride -> conflict-free ldmatrix
#define TS (128 * PADW)               // elems per tile array
#define TSB (TS * 2)                  // bytes
#define STAGE_BYTES (4 * TSB)         // Ah,Al,Bh,Bl
#define SMEM_TOT (3 * STAGE_BYTES)    // 221184 B

struct GP {
    const bf16* Bh[3];
    const bf16* Bl[3];
    float* C[3];
    const float* R[3];
};

template <int RES>
__global__ void __launch_bounds__(256, 1)
mgemm(const bf16* __restrict__ Ah, const bf16* __restrict__ Al,
      GP p, int M, int N, int K) {
    extern __shared__ char dsm[];
    const bf16* __restrict__ Bh = p.Bh[blockIdx.z];
    const bf16* __restrict__ Bl = p.Bl[blockIdx.z];
    float* __restrict__ C = p.C[blockIdx.z];
    const float* __restrict__ Rsd = RES ? p.R[blockIdx.z] : nullptr;

    const int tid = threadIdx.x;
    const int lane = tid & 31;
    const int wid = tid >> 5;
    const int wm = wid & 1;
    const int wn = wid >> 1;
    const int row0 = blockIdx.y * 128, col0 = blockIdx.x * 128;

    const bf16* At_h = Ah + (size_t)row0 * K;
    const bf16* At_l = Al + (size_t)row0 * K;
    const bf16* Bt_h = Bh + (size_t)col0 * K;
    const bf16* Bt_l = Bl + (size_t)col0 * K;

    // per-thread cp.async slots: 4 x 16B per array per chunk (128 rows x 64 cols bf16)
    int rw[4], cl[4], soff[4];
    #pragma unroll
    for (int i = 0; i < 4; i++) {
        int t = i * 256 + tid;        // 0..1023
        rw[i] = t >> 3;               // row 0..127
        cl[i] = (t & 7) * 8;          // bf16 col: 0,8,...,56
        soff[i] = (rw[i] * PADW + cl[i]) * 2;
    }
    const uint32_t smem_base = smem_u32(dsm);

    float acc[4][4][4];
    #pragma unroll
    for (int mt = 0; mt < 4; mt++)
        #pragma unroll
        for (int nt = 0; nt < 4; nt++)
            #pragma unroll
            for (int j = 0; j < 4; j++) acc[mt][nt][j] = 0.f;

    const int aRow = wm * 64 + (lane & 15);
    const int aCol = (lane >> 4) * 8;
    const int bRow = wn * 32 + (lane >> 4) * 8 + (lane & 7);
    const int bCol = ((lane >> 3) & 1) * 8;

    const int nchunk = K / BK;

    // issue one chunk's 16 cp.async into stage s
    auto issue = [&](int c, int s) {
        uint32_t sb = smem_base + s * STAGE_BYTES;
        int gco = c * BK;
        #pragma unroll
        for (int i = 0; i < 4; i++) {
            size_t go = (size_t)rw[i] * K + gco + cl[i];
            cpasync16(sb + soff[i],           At_h + go);
            cpasync16(sb + TSB + soff[i],     At_l + go);
            cpasync16(sb + 2 * TSB + soff[i], Bt_h + go);
            cpasync16(sb + 3 * TSB + soff[i], Bt_l + go);
        }
    };

    issue(0, 0); CP_COMMIT();
    issue(1, 1); CP_COMMIT();

    for (int c = 0; c < nchunk; c++) {
        cp_wait(c + 1 < nchunk ? 1 : 0);
        __syncthreads();
        if (c + 2 < nchunk) { issue(c + 2, (c + 2) % 3); CP_COMMIT(); }

        const uint32_t sbase = smem_base + (c % 3) * STAGE_BYTES;
        const uint32_t aH = sbase, aL = sbase + TSB;
        const uint32_t bH = sbase + 2 * TSB, bL = sbase + 3 * TSB;

        #pragma unroll
        for (int kt = 0; kt < 4; kt++) {
            uint32_t ah[4][4], al[4][4], bh[4][2], bl[4][2];
            #pragma unroll
            for (int mt = 0; mt < 4; mt++) {
                uint32_t off = ((uint32_t)(aRow + mt * 16) * PADW + aCol + kt * 16) * 2;
                ldmx4(ah[mt][0], ah[mt][1], ah[mt][2], ah[mt][3], aH + off);
                ldmx4(al[mt][0], al[mt][1], al[mt][2], al[mt][3], aL + off);
            }
            #pragma unroll
            for (int n2 = 0; n2 < 2; n2++) {
                uint32_t off = ((uint32_t)(bRow + n2 * 16) * PADW + bCol + kt * 16) * 2;
                uint32_t r0, r1, r2, r3;
                ldmx4(r0, r1, r2, r3, bH + off);
                bh[n2 * 2][0] = r0; bh[n2 * 2][1] = r1;
                bh[n2 * 2 + 1][0] = r2; bh[n2 * 2 + 1][1] = r3;
                ldmx4(r0, r1, r2, r3, bL + off);
                bl[n2 * 2][0] = r0; bl[n2 * 2][1] = r1;
                bl[n2 * 2 + 1][0] = r2; bl[n2 * 2 + 1][1] = r3;
            }
            #pragma unroll
            for (int mt = 0; mt < 4; mt++)
                #pragma unroll
                for (int nt = 0; nt < 4; nt++) {
                    mma16816(acc[mt][nt], ah[mt], bh[nt]);
                    mma16816(acc[mt][nt], ah[mt], bl[nt]);
                    mma16816(acc[mt][nt], al[mt], bh[nt]);
                }
        }
    }

    #pragma unroll
    for (int mt = 0; mt < 4; mt++) {
        int r0g = row0 + wm * 64 + mt * 16 + (lane >> 2);
        #pragma unroll
        for (int nt = 0; nt < 4; nt++) {
            int cg = col0 + wn * 32 + nt * 8 + (lane & 3) * 2;
            float2 v0 = make_float2(acc[mt][nt][0], acc[mt][nt][1]);
            float2 v1 = make_float2(acc[mt][nt][2], acc[mt][nt][3]);
            if (RES) {
                float2 q0 = *(const float2*)(Rsd + (size_t)r0g * N + cg);
                float2 q1 = *(const float2*)(Rsd + (size_t)(r0g + 8) * N + cg);
                v0.x += q0.x; v0.y += q0.y;
                v1.x += q1.x; v1.y += q1.y;
            }
            *(float2*)(C + (size_t)r0g * N + cg) = v0;
            *(float2*)(C + (size_t)(r0g + 8) * N + cg) = v1;
        }
    }
}

// ---------------- batched weight splitter ----------------
struct S6 {
    const float* s[6];
    bf16* h[6];
    bf16* l[6];
    int n4[6];   // element count / 4
};
__global__ void split6_k(S6 p) {
    int z = blockIdx.y;
    int i4 = blockIdx.x * 256 + threadIdx.x;
    if (i4 >= p.n4[z]) return;
    float4 v = ((const float4*)p.s[z])[i4];
    bf16 h0, h1, h2, h3, l0, l1, l2, l3;
    split1(v.x, h0, l0); split1(v.y, h1, l1);
    split1(v.z, h2, l2); split1(v.w, h3, l3);
    ((uint2*)p.h[z])[i4] = make_uint2(pack_bf16x2((float)h0, (float)h1) ,
                                      pack_bf16x2((float)h2, (float)h3));
    // pack_bf16x2 re-rounds; write raw instead:
    __nv_bfloat162 hh0; hh0.x = h0; hh0.y = h1;
    __nv_bfloat162 hh1; hh1.x = h2; hh1.y = h3;
    __nv_bfloat162 ll0; ll0.x = l0; ll0.y = l1;
    __nv_bfloat162 ll1; ll1.x = l2; ll1.y = l3;
    ((uint2*)p.h[z])[i4] = make_uint2(*(uint32_t*)&hh0, *(uint32_t*)&hh1);
    ((uint2*)p.l[z])[i4] = make_uint2(*(uint32_t*)&ll0, *(uint32_t*)&ll1);
}

// ---------------- RMSNorm (+ bf16 split outputs) ----------------
__global__ void rmsnorm_k(const float* __restrict__ x, const float* __restrict__ w,
                          float* __restrict__ out, bf16* __restrict__ oh,
                          bf16* __restrict__ ol) {
    int row = blockIdx.x;
    const float* xr = x + row * HID;
    float ss = 0.f;
    for (int i = threadIdx.x; i < HID; i += 256) { float v = xr[i]; ss += v * v; }
    #pragma unroll
    for (int m = 16; m; m >>= 1) ss += __shfl_xor_sync(0xffffffffu, ss, m);
    __shared__ float red[8];
    if ((threadIdx.x & 31) == 0) red[threadIdx.x >> 5] = ss;
    __syncthreads();
    if (threadIdx.x < 8) {
        float r = red[threadIdx.x];
        #pragma unroll
        for (int m = 4; m; m >>= 1) r += __shfl_xor_sync(0xffu, r, m);
        if (threadIdx.x == 0) red[0] = r;
    }
    __syncthreads();
    float scale = rsqrtf(red[0] * (1.0f / (float)HID) + 1e-6f);
    for (int i = threadIdx.x; i < HID; i += 256) {
        float y = xr[i] * scale * w[i];
        if (out) out[row * HID + i] = y;
        bf16 h, l;
        split1(y, h, l);
        oh[row * HID + i] = h;
        ol[row * HID + i] = l;
    }
}

// ---------------- fused causal depthwise conv (K=4) + silu(silu(.)), 3 streams ----------------
struct CP3 { const float* in[3]; const float* w[3]; float* out[3]; };

__global__ void conv_silu2_k(CP3 p) {
    int z = blockIdx.y;
    const float* __restrict__ in = p.in[z];
    const float* __restrict__ w  = p.w[z];
    float* __restrict__ out = p.out[z];
    int idx = blockIdx.x * blockDim.x + threadIdx.x;
    int c = idx & (HID - 1);
    int t = idx >> 11;
    const float* wc = w + c * 4;
    float acc = 0.f;
    #pragma unroll
    for (int j = 0; j < 4; j++) {
        int ti = t - 3 + j;
        if (ti >= 0) acc = fmaf(in[ti * HID + c], wc[j], acc);
    }
    float s1 = acc / (1.f + expf(-acc));
    float s2 = s1 / (1.f + expf(-s1));
    out[idx] = s2;
}

// ---------------- per-head L2 norm (in-place), 2 streams ----------------
__global__ void l2norm_k(float* __restrict__ pq, float* __restrict__ pk) {
    float* p = blockIdx.y ? pk : pq;
    int t = blockIdx.x;
    int h = threadIdx.x >> 5, l = threadIdx.x & 31;
    float* r = p + t * HID + h * HD;
    float a = r[l], b = r[l + 32];
    float ss = a * a + b * b;
    #pragma unroll
    for (int m = 16; m; m >>= 1) ss += __shfl_xor_sync(0xffffffffu, ss, m);
    float inv = 1.f / fmaxf(sqrtf(ss), 1e-12f);
    r[l] = a * inv;
    r[l + 32] = b * inv;
}

// ---------------- beta = sigmoid(h @ Wbeta^T) ----------------
__global__ void beta_k(const float* __restrict__ hbuf, const float* __restrict__ Wb,
                       float* __restrict__ beta) {
    int t = blockIdx.x;
    int hh = threadIdx.x >> 5, l = threadIdx.x & 31;
    const float* hr = hbuf + t * HID;
    const float* wr = Wb + hh * HID;
    float s = 0.f;
    for (int i = l; i < HID; i += 32) s = fmaf(hr[i], wr[i], s);
    #pragma unroll
    for (int m = 16; m; m >>= 1) s += __shfl_xor_sync(0xffffffffu, s, m);
    if (l == 0) beta[t * NH + hh] = 1.f / (1.f + expf(-s));
}

// ---------------- delta scan ----------------
__global__ void delta_scan_k(const float* __restrict__ kb, const float* __restrict__ qb,
                             const float* __restrict__ vb, const float* __restrict__ betab,
                             float* __restrict__ ob, float* __restrict__ Sout) {
    int gtid = blockIdx.x * blockDim.x + threadIdx.x;
    int sub  = gtid & 3;
    int task = gtid >> 2;
    int head = task >> 6;
    int row  = task & 63;
    int c0   = sub << 4;

    float S[16];
    #pragma unroll
    for (int j = 0; j < 16; j++) S[j] = 0.f;

    const float* kp = kb + head * HD + c0;
    const float* qp = qb + head * HD + c0;
    const float* vp = vb + head * HD + row;
    const float* bp = betab + head;
    float* op = ob + head * HD + row;

    for (int t = 0; t < TT; t++) {
        float kk[16], qq[16];
        *(float4*)(kk)      = *(const float4*)(kp);
        *(float4*)(kk + 4)  = *(const float4*)(kp + 4);
        *(float4*)(kk + 8)  = *(const float4*)(kp + 8);
        *(float4*)(kk + 12) = *(const float4*)(kp + 12);
        *(float4*)(qq)      = *(const float4*)(qp);
        *(float4*)(qq + 4)  = *(const float4*)(qp + 4);
        *(float4*)(qq + 8)  = *(const float4*)(qp + 8);
        *(float4*)(qq + 12) = *(const float4*)(qp + 12);
        float vt = *vp;
        float bt = *bp;

        float a = 0.f, b = 0.f, c = 0.f;
        #pragma unroll
        for (int j = 0; j < 16; j++) {
            a = fmaf(S[j], kk[j], a);
            b = fmaf(S[j], qq[j], b);
            c = fmaf(kk[j], qq[j], c);
        }
        a += __shfl_xor_sync(0xffffffffu, a, 1);
        b += __shfl_xor_sync(0xffffffffu, b, 1);
        c += __shfl_xor_sync(0xffffffffu, c, 1);
        a += __shfl_xor_sync(0xffffffffu, a, 2);
        b += __shfl_xor_sync(0xffffffffu, b, 2);
        c += __shfl_xor_sync(0xffffffffu, c, 2);

        float coef = bt * (a - vt);
        float ot = b - coef * c;
        #pragma unroll
        for (int j = 0; j < 16; j++) S[j] = fmaf(-coef, kk[j], S[j]);
        if (sub == 0) op[t * HID] = ot;

        kp += HID; qp += HID; vp += HID; bp += NH;
    }

    #pragma unroll
    for (int j = 0; j < 16; j++)
        Sout[head * HD * HD + row * HD + c0 + j] = S[j];
}

// ---------------- SwiGLU elementwise -> bf16 split ----------------
__global__ void swiglu_k(const float* __restrict__ g, const float* __restrict__ u,
                         bf16* __restrict__ oh, bf16* __restrict__ ol, int n) {
    int i = blockIdx.x * blockDim.x + threadIdx.x;
    if (i < n) {
        float x = g[i];
        float y = (x / (1.f + expf(-x))) * u[i];
        bf16 h, l;
        split1(y, h, l);
        oh[i] = h;
        ol[i] = l;
    }
}

// ---------------- launch ----------------
extern "C" void kernel_launch(void* const* d_in, const int* in_sizes, int n_in,
                              void* d_out, int out_size) {
    const float* x_in   = (const float*)d_in[0];
    const float* attn_w = (const float*)d_in[1];
    const float* Wq     = (const float*)d_in[2];
    const float* Wk     = (const float*)d_in[3];
    const float* Wv     = (const float*)d_in[4];
    const float* cq     = (const float*)d_in[5];
    const float* ck     = (const float*)d_in[6];
    const float* cv     = (const float*)d_in[7];
    const float* Wb     = (const float*)d_in[8];
    const float* out_w  = (const float*)d_in[9];
    const float* Wout   = (const float*)d_in[10];
    const float* mlp_w  = (const float*)d_in[11];
    const float* Wg     = (const float*)d_in[12];
    const float* Wu     = (const float*)d_in[13];
    const float* Wd     = (const float*)d_in[14];

    float *h, *qr, *kr, *vr, *q, *k, *v, *beta, *o, *on, *x1, *h2, *gate, *up, *Ssc;
    cudaGetSymbolAddress((void**)&h,   g_h);
    cudaGetSymbolAddress((void**)&qr,  g_qr);
    cudaGetSymbolAddress((void**)&kr,  g_kr);
    cudaGetSymbolAddress((void**)&vr,  g_vr);
    cudaGetSymbolAddress((void**)&q,   g_q);
    cudaGetSymbolAddress((void**)&k,   g_k);
    cudaGetSymbolAddress((void**)&v,   g_v);
    cudaGetSymbolAddress((void**)&beta,g_beta);
    cudaGetSymbolAddress((void**)&o,   g_o);
    cudaGetSymbolAddress((void**)&on,  g_on);
    cudaGetSymbolAddress((void**)&x1,  g_x1);
    cudaGetSymbolAddress((void**)&h2,  g_h2);
    cudaGetSymbolAddress((void**)&gate,g_gate);
    cudaGetSymbolAddress((void**)&up,  g_up);
    cudaGetSymbolAddress((void**)&Ssc, g_Ssc);

    bf16 *hh,*hl,*onh,*onl,*h2h,*h2l,*acth,*actl;
    bf16 *wqh,*wql,*wkh,*wkl,*wvh,*wvl,*woh,*wol,*wgh,*wgl,*wuh,*wul,*wdh,*wdl;
    cudaGetSymbolAddress((void**)&hh,  g_hh);   cudaGetSymbolAddress((void**)&hl,  g_hl);
    cudaGetSymbolAddress((void**)&onh, g_onh);  cudaGetSymbolAddress((void**)&onl, g_onl);
    cudaGetSymbolAddress((void**)&h2h, g_h2h);  cudaGetSymbolAddress((void**)&h2l, g_h2l);
    cudaGetSymbolAddress((void**)&acth,g_acth); cudaGetSymbolAddress((void**)&actl,g_actl);
    cudaGetSymbolAddress((void**)&wqh, g_wqh);  cudaGetSymbolAddress((void**)&wql, g_wql);
    cudaGetSymbolAddress((void**)&wkh, g_wkh);  cudaGetSymbolAddress((void**)&wkl, g_wkl);
    cudaGetSymbolAddress((void**)&wvh, g_wvh);  cudaGetSymbolAddress((void**)&wvl, g_wvl);
    cudaGetSymbolAddress((void**)&woh, g_woh);  cudaGetSymbolAddress((void**)&wol, g_wol);
    cudaGetSymbolAddress((void**)&wgh, g_wgh);  cudaGetSymbolAddress((void**)&wgl, g_wgl);
    cudaGetSymbolAddress((void**)&wuh, g_wuh);  cudaGetSymbolAddress((void**)&wul, g_wul);
    cudaGetSymbolAddress((void**)&wdh, g_wdh);  cudaGetSymbolAddress((void**)&wdl, g_wdl);

    float* out_x = (float*)d_out;
    float* Sdst = (out_size >= TT * HID + NH * HD * HD) ? (out_x + TT * HID) : Ssc;

    cudaFuncSetAttribute(mgemm<0>, cudaFuncAttributeMaxDynamicSharedMemorySize, SMEM_TOT);
    cudaFuncSetAttribute(mgemm<1>, cudaFuncAttributeMaxDynamicSharedMemorySize, SMEM_TOT);

    // ---- split weights (once per launch) ----
    {
        S6 sp;
        sp.s[0] = Wq;  sp.h[0] = wqh; sp.l[0] = wql; sp.n4[0] = HID * HID / 4;
        sp.s[1] = Wk;  sp.h[1] = wkh; sp.l[1] = wkl; sp.n4[1] = HID * HID / 4;
        sp.s[2] = Wv;  sp.h[2] = wvh; sp.l[2] = wvl; sp.n4[2] = HID * HID / 4;
        sp.s[3] = Wout;sp.h[3] = woh; sp.l[3] = wol; sp.n4[3] = HID * HID / 4;
        sp.s[4] = Wg;  sp.h[4] = wgh; sp.l[4] = wgl; sp.n4[4] = INTER * HID / 4;
        sp.s[5] = Wu;  sp.h[5] = wuh; sp.l[5] = wul; sp.n4[5] = INTER * HID / 4;
        dim3 g((INTER * HID / 4 + 255) / 256, 6);
        split6_k<<<g, 256>>>(sp);
        S6 sp2;
        sp2.s[0] = Wd; sp2.h[0] = wdh; sp2.l[0] = wdl; sp2.n4[0] = HID * INTER / 4;
        for (int i = 1; i < 6; i++) { sp2.s[i] = Wd; sp2.h[i] = wdh; sp2.l[i] = wdl; sp2.n4[i] = 0; }
        dim3 g2((HID * INTER / 4 + 255) / 256, 1);
        split6_k<<<g2, 256>>>(sp2);
    }

    // ---- attention sub-block ----
    rmsnorm_k<<<TT, 256>>>(x_in, attn_w, h, hh, hl);

    {   // fused q/k/v projection
        GP p;
        p.Bh[0] = wqh; p.Bl[0] = wql; p.C[0] = qr; p.R[0] = nullptr;
        p.Bh[1] = wkh; p.Bl[1] = wkl; p.C[1] = kr; p.R[1] = nullptr;
        p.Bh[2] = wvh; p.Bl[2] = wvl; p.C[2] = vr; p.R[2] = nullptr;
        dim3 g(HID / 128, TT / 128, 3);
        mgemm<0><<<g, 256, SMEM_TOT>>>(hh, hl, p, TT, HID, HID);
    }

    {   // fused conv + double-silu for q/k/v
        CP3 cp = {{qr, kr, vr}, {cq, ck, cv}, {q, k, v}};
        dim3 g((TT * HID) / 256, 3);
        conv_silu2_k<<<g, 256>>>(cp);
    }

    l2norm_k<<<dim3(TT, 2), 1024>>>(q, k);
    beta_k<<<TT, 1024>>>(h, Wb, beta);

    delta_scan_k<<<64, 128>>>(k, q, v, beta, o, Sdst);

    rmsnorm_k<<<TT, 256>>>(o, out_w, nullptr, onh, onl);
    {   // output projection + residual
        GP p;
        p.Bh[0] = woh; p.Bl[0] = wol; p.C[0] = x1; p.R[0] = x_in;
        for (int i = 1; i < 3; i++) { p.Bh[i] = nullptr; p.Bl[i] = nullptr; p.C[i] = nullptr; p.R[i] = nullptr; }
        dim3 g(HID / 128, TT / 128, 1);
        mgemm<1><<<g, 256, SMEM_TOT>>>(onh, onl, p, TT, HID, HID);
    }

    // ---- MLP sub-block ----
    rmsnorm_k<<<TT, 256>>>(x1, mlp_w, nullptr, h2h, h2l);
    {   // fused gate + up projection
        GP p;
        p.Bh[0] = wgh; p.Bl[0] = wgl; p.C[0] = gate; p.R[0] = nullptr;
        p.Bh[1] = wuh; p.Bl[1] = wul; p.C[1] = up;   p.R[1] = nullptr;
        p.Bh[2] = nullptr; p.Bl[2] = nullptr; p.C[2] = nullptr; p.R[2] = nullptr;
        dim3 g(INTER / 128, TT / 128, 2);
        mgemm<0><<<g, 256, SMEM_TOT>>>(h2h, h2l, p, TT, INTER, HID);
    }
    swiglu_k<<<(TT * INTER) / 256, 256>>>(gate, up, acth, actl, TT * INTER);
    {   // down projection + residual
        GP p;
        p.Bh[0] = wdh; p.Bl[0] = wdl; p.C[0] = out_x; p.R[0] = x1;
        for (int i = 1; i < 3; i++) { p.Bh[i] = nullptr; p.Bl[i] = nullptr; p.C[i] = nullptr; p.R[i] = nullptr; }
        dim3 g(HID / 128, TT / 128, 1);
        mgemm<1><<<g, 256, SMEM_TOT>>>(acth, actl, p, TT, HID, INTER);
    }
}

// round 9
// speedup vs baseline: 1.2006x; 1.2006x over previous
#include <cuda_runtime.h>
#include <cuda_fp16.h>
#include <math.h>
#include <stdint.h>

#define HID 2048
#define TT 1024
#define NH 32
#define HD 64
#define INTER 5632

typedef __half f16;

// ---------------- scratch (no allocations allowed) ----------------
__device__ float g_h[TT*HID];
__device__ float g_qr[TT*HID];
__device__ float g_kr[TT*HID];
__device__ float g_vr[TT*HID];
__device__ float g_q[TT*HID];
__device__ float g_k[TT*HID];
__device__ float g_v[TT*HID];
__device__ float g_beta[TT*NH];
__device__ float g_o[TT*HID];
__device__ float g_x1[TT*HID];
__device__ float g_gate[TT*INTER];
__device__ float g_up[TT*INTER];
__device__ float g_Ssc[NH*HD*HD];

// fp16 operand buffers
__device__ f16 g_hh[TT*HID];       // rmsnorm(x) fp16
__device__ f16 g_onh[TT*HID];      // rmsnorm(o) fp16
__device__ f16 g_h2h[TT*HID];      // rmsnorm(x1) fp16
__device__ f16 g_acth[TT*INTER];   // swiglu fp16
__device__ f16 g_wq[HID*HID], g_wk[HID*HID], g_wv[HID*HID], g_wo[HID*HID];
__device__ f16 g_wg[INTER*HID], g_wu[INTER*HID], g_wd[HID*INTER];

// ================= helpers =================
__device__ __forceinline__ uint32_t smem_u32(const void* p) {
    uint32_t a;
    asm("{ .reg .u64 t; cvta.to.shared.u64 t, %1; cvt.u32.u64 %0, t; }" : "=r"(a) : "l"(p));
    return a;
}
__device__ __forceinline__ void ldmx4(uint32_t& r0, uint32_t& r1, uint32_t& r2, uint32_t& r3,
                                      uint32_t addr) {
    asm volatile("ldmatrix.sync.aligned.m8n8.x4.shared.b16 {%0,%1,%2,%3}, [%4];"
                 : "=r"(r0), "=r"(r1), "=r"(r2), "=r"(r3) : "r"(addr));
}
__device__ __forceinline__ void mma16816(float* c, const uint32_t* a, const uint32_t* b) {
    asm volatile(
        "mma.sync.aligned.m16n8k16.row.col.f32.f16.f16.f32 "
        "{%0,%1,%2,%3}, {%4,%5,%6,%7}, {%8,%9}, {%0,%1,%2,%3};"
        : "+f"(c[0]), "+f"(c[1]), "+f"(c[2]), "+f"(c[3])
        : "r"(a[0]), "r"(a[1]), "r"(a[2]), "r"(a[3]), "r"(b[0]), "r"(b[1]));
}
__device__ __forceinline__ void cpasync16(uint32_t saddr, const void* gptr) {
    asm volatile("cp.async.ca.shared.global [%0], [%1], 16;" :: "r"(saddr), "l"(gptr));
}
#define CP_COMMIT() asm volatile("cp.async.commit_group;" ::: "memory")
__device__ __forceinline__ void cp_wait(int pend) {
    if (pend <= 0)      asm volatile("cp.async.wait_group 0;" ::: "memory");
    else if (pend == 1) asm volatile("cp.async.wait_group 1;" ::: "memory");
    else                asm volatile("cp.async.wait_group 2;" ::: "memory");
}

// ================= fp16 tensor GEMM: C[M,N] = A[M,K] @ B[N,K]^T (+Rsd) =================
// single-product fp16 (fp32 accum). 128x128 CTA tile, BK=64, 4-stage cp.async ring,
// one barrier per chunk. 8 warps (2x4), 64x32 warp tile.
#define BK 64
#define PADW 72                       // 144B row stride -> conflict-free ldmatrix
#define TILE_B (128 * PADW * 2)       // bytes per operand tile
#define STAGE_BYTES (2 * TILE_B)      // A + B
#define NSTAGE 4
#define SMEM_TOT (NSTAGE * STAGE_BYTES)  // 147456 B

struct GP {
    const f16* B[3];
    float* C[3];
    const float* R[3];
};

template <int RES>
__global__ void __launch_bounds__(256, 1)
mgemm(const f16* __restrict__ A, GP p, int M, int N, int K) {
    extern __shared__ char dsm[];
    const f16* __restrict__ B = p.B[blockIdx.z];
    float* __restrict__ C = p.C[blockIdx.z];
    const float* __restrict__ Rsd = RES ? p.R[blockIdx.z] : nullptr;

    const int tid = threadIdx.x;
    const int lane = tid & 31;
    const int wid = tid >> 5;
    const int wm = wid & 1;
    const int wn = wid >> 1;
    const int row0 = blockIdx.y * 128, col0 = blockIdx.x * 128;

    const f16* At = A + (size_t)row0 * K;
    const f16* Bt = B + (size_t)col0 * K;

    // per-thread cp.async slots: 4 x 16B per operand per chunk (128 rows x 64 cols fp16)
    int rw[4], cl[4], soff[4];
    #pragma unroll
    for (int i = 0; i < 4; i++) {
        int t = i * 256 + tid;        // 0..1023
        rw[i] = t >> 3;               // row 0..127
        cl[i] = (t & 7) * 8;          // fp16 col: 0,8,...,56
        soff[i] = (rw[i] * PADW + cl[i]) * 2;
    }
    const uint32_t smem_base = smem_u32(dsm);

    float acc[4][4][4];
    #pragma unroll
    for (int mt = 0; mt < 4; mt++)
        #pragma unroll
        for (int nt = 0; nt < 4; nt++)
            #pragma unroll
            for (int j = 0; j < 4; j++) acc[mt][nt][j] = 0.f;

    const int aRow = wm * 64 + (lane & 15);
    const int aCol = (lane >> 4) * 8;
    const int bRow = wn * 32 + (lane >> 4) * 8 + (lane & 7);
    const int bCol = ((lane >> 3) & 1) * 8;

    const int nchunk = K / BK;

    auto issue = [&](int c) {
        uint32_t sb = smem_base + (c & (NSTAGE - 1)) * STAGE_BYTES;
        int gco = c * BK;
        #pragma unroll
        for (int i = 0; i < 4; i++) {
            size_t go = (size_t)rw[i] * K + gco + cl[i];
            cpasync16(sb + soff[i],          At + go);
            cpasync16(sb + TILE_B + soff[i], Bt + go);
        }
    };

    issue(0); CP_COMMIT();
    issue(1); CP_COMMIT();
    issue(2); CP_COMMIT();

    for (int c = 0; c < nchunk; c++) {
        int pend = nchunk - c - 1; if (pend > 2) pend = 2;
        cp_wait(pend);
        __syncthreads();
        if (c + 3 < nchunk) { issue(c + 3); CP_COMMIT(); }

        const uint32_t sbase = smem_base + (c & (NSTAGE - 1)) * STAGE_BYTES;
        const uint32_t aH = sbase;
        const uint32_t bH = sbase + TILE_B;

        #pragma unroll
        for (int kt = 0; kt < 4; kt++) {
            uint32_t ah[4][4], bh[4][2];
            #pragma unroll
            for (int mt = 0; mt < 4; mt++) {
                uint32_t off = ((uint32_t)(aRow + mt * 16) * PADW + aCol + kt * 16) * 2;
                ldmx4(ah[mt][0], ah[mt][1], ah[mt][2], ah[mt][3], aH + off);
            }
            #pragma unroll
            for (int n2 = 0; n2 < 2; n2++) {
                uint32_t off = ((uint32_t)(bRow + n2 * 16) * PADW + bCol + kt * 16) * 2;
                uint32_t r0, r1, r2, r3;
                ldmx4(r0, r1, r2, r3, bH + off);
                bh[n2 * 2][0] = r0;     bh[n2 * 2][1] = r1;
                bh[n2 * 2 + 1][0] = r2; bh[n2 * 2 + 1][1] = r3;
            }
            #pragma unroll
            for (int mt = 0; mt < 4; mt++)
                #pragma unroll
                for (int nt = 0; nt < 4; nt++)
                    mma16816(acc[mt][nt], ah[mt], bh[nt]);
        }
    }

    #pragma unroll
    for (int mt = 0; mt < 4; mt++) {
        int r0g = row0 + wm * 64 + mt * 16 + (lane >> 2);
        #pragma unroll
        for (int nt = 0; nt < 4; nt++) {
            int cg = col0 + wn * 32 + nt * 8 + (lane & 3) * 2;
            float2 v0 = make_float2(acc[mt][nt][0], acc[mt][nt][1]);
            float2 v1 = make_float2(acc[mt][nt][2], acc[mt][nt][3]);
            if (RES) {
                float2 q0 = *(const float2*)(Rsd + (size_t)r0g * N + cg);
                float2 q1 = *(const float2*)(Rsd + (size_t)(r0g + 8) * N + cg);
                v0.x += q0.x; v0.y += q0.y;
                v1.x += q1.x; v1.y += q1.y;
            }
            *(float2*)(C + (size_t)r0g * N + cg) = v0;
            *(float2*)(C + (size_t)(r0g + 8) * N + cg) = v1;
        }
    }
}

// ---------------- batched fp32 -> fp16 weight converter ----------------
struct C7 {
    const float* s[7];
    f16* d[7];
    int n4[7];
};
__global__ void cvt7_k(C7 p) {
    int z = blockIdx.y;
    int i4 = blockIdx.x * 256 + threadIdx.x;
    if (i4 >= p.n4[z]) return;
    float4 v = ((const float4*)p.s[z])[i4];
    __half2 h0 = __floats2half2_rn(v.x, v.y);
    __half2 h1 = __floats2half2_rn(v.z, v.w);
    ((uint2*)p.d[z])[i4] = make_uint2(*(uint32_t*)&h0, *(uint32_t*)&h1);
}

// ---------------- RMSNorm (fp32 optional + fp16 out) ----------------
__global__ void rmsnorm_k(const float* __restrict__ x, const float* __restrict__ w,
                          float* __restrict__ out, f16* __restrict__ oh) {
    int row = blockIdx.x;
    const float* xr = x + row * HID;
    float ss = 0.f;
    for (int i = threadIdx.x; i < HID; i += 256) { float v = xr[i]; ss += v * v; }
    #pragma unroll
    for (int m = 16; m; m >>= 1) ss += __shfl_xor_sync(0xffffffffu, ss, m);
    __shared__ float red[8];
    if ((threadIdx.x & 31) == 0) red[threadIdx.x >> 5] = ss;
    __syncthreads();
    if (threadIdx.x < 8) {
        float r = red[threadIdx.x];
        #pragma unroll
        for (int m = 4; m; m >>= 1) r += __shfl_xor_sync(0xffu, r, m);
        if (threadIdx.x == 0) red[0] = r;
    }
    __syncthreads();
    float scale = rsqrtf(red[0] * (1.0f / (float)HID) + 1e-6f);
    for (int i = threadIdx.x; i < HID; i += 256) {
        float y = xr[i] * scale * w[i];
        if (out) out[row * HID + i] = y;
        oh[row * HID + i] = __float2half_rn(y);
    }
}

// ---------------- fused causal depthwise conv (K=4) + silu(silu(.)), 3 streams ----------------
struct CP3 { const float* in[3]; const float* w[3]; float* out[3]; };

__global__ void conv_silu2_k(CP3 p) {
    int z = blockIdx.y;
    const float* __restrict__ in = p.in[z];
    const float* __restrict__ w  = p.w[z];
    float* __restrict__ out = p.out[z];
    int idx = blockIdx.x * blockDim.x + threadIdx.x;
    int c = idx & (HID - 1);
    int t = idx >> 11;
    const float* wc = w + c * 4;
    float acc = 0.f;
    #pragma unroll
    for (int j = 0; j < 4; j++) {
        int ti = t - 3 + j;
        if (ti >= 0) acc = fmaf(in[ti * HID + c], wc[j], acc);
    }
    float s1 = acc / (1.f + expf(-acc));
    float s2 = s1 / (1.f + expf(-s1));
    out[idx] = s2;
}

// ---------------- per-head L2 norm (in-place), 2 streams ----------------
__global__ void l2norm_k(float* __restrict__ pq, float* __restrict__ pk) {
    float* p = blockIdx.y ? pk : pq;
    int t = blockIdx.x;
    int h = threadIdx.x >> 5, l = threadIdx.x & 31;
    float* r = p + t * HID + h * HD;
    float a = r[l], b = r[l + 32];
    float ss = a * a + b * b;
    #pragma unroll
    for (int m = 16; m; m >>= 1) ss += __shfl_xor_sync(0xffffffffu, ss, m);
    float inv = 1.f / fmaxf(sqrtf(ss), 1e-12f);
    r[l] = a * inv;
    r[l + 32] = b * inv;
}

// ---------------- beta = sigmoid(h @ Wbeta^T) ----------------
__global__ void beta_k(const float* __restrict__ hbuf, const float* __restrict__ Wb,
                       float* __restrict__ beta) {
    int t = blockIdx.x;
    int hh = threadIdx.x >> 5, l = threadIdx.x & 31;
    const float* hr = hbuf + t * HID;
    const float* wr = Wb + hh * HID;
    float s = 0.f;
    for (int i = l; i < HID; i += 32) s = fmaf(hr[i], wr[i], s);
    #pragma unroll
    for (int m = 16; m; m >>= 1) s += __shfl_xor_sync(0xffffffffu, s, m);
    if (l == 0) beta[t * NH + hh] = 1.f / (1.f + expf(-s));
}

// ---------------- delta scan (4-chain dots + next-step prefetch) ----------------
__global__ void delta_scan_k(const float* __restrict__ kb, const float* __restrict__ qb,
                             const float* __restrict__ vb, const float* __restrict__ betab,
                             float* __restrict__ ob, float* __restrict__ Sout) {
    int gtid = blockIdx.x * blockDim.x + threadIdx.x;
    int sub  = gtid & 3;
    int task = gtid >> 2;
    int head = task >> 6;
    int row  = task & 63;
    int c0   = sub << 4;

    float S[16];
    #pragma unroll
    for (int j = 0; j < 16; j++) S[j] = 0.f;

    const float* kp = kb + head * HD + c0;
    const float* qp = qb + head * HD + c0;
    const float* vp = vb + head * HD + row;
    const float* bp = betab + head;
    float* op = ob + head * HD + row;

    float kk[16], qq[16], vt, bt;
    #pragma unroll
    for (int j = 0; j < 16; j += 4) {
        *(float4*)(kk + j) = *(const float4*)(kp + j);
        *(float4*)(qq + j) = *(const float4*)(qp + j);
    }
    vt = *vp; bt = *bp;

    for (int t = 0; t < TT; t++) {
        float nk[16], nq[16], nvt = 0.f, nbt = 0.f;
        if (t + 1 < TT) {
            const float* kp1 = kp + HID;
            const float* qp1 = qp + HID;
            #pragma unroll
            for (int j = 0; j < 16; j += 4) {
                *(float4*)(nk + j) = *(const float4*)(kp1 + j);
                *(float4*)(nq + j) = *(const float4*)(qp1 + j);
            }
            nvt = vp[HID]; nbt = bp[NH];
        }

        // 4-way split dot chains to shorten the serial FMA path
        float a0 = 0.f, a1 = 0.f, a2 = 0.f, a3 = 0.f;
        float b0 = 0.f, b1 = 0.f, b2 = 0.f, b3 = 0.f;
        float c0s = 0.f, c1s = 0.f, c2s = 0.f, c3s = 0.f;
        #pragma unroll
        for (int j = 0; j < 4; j++) {
            a0 = fmaf(S[j], kk[j], a0);           a1 = fmaf(S[j + 4], kk[j + 4], a1);
            a2 = fmaf(S[j + 8], kk[j + 8], a2);   a3 = fmaf(S[j + 12], kk[j + 12], a3);
            b0 = fmaf(S[j], qq[j], b0);           b1 = fmaf(S[j + 4], qq[j + 4], b1);
            b2 = fmaf(S[j + 8], qq[j + 8], b2);   b3 = fmaf(S[j + 12], qq[j + 12], b3);
            c0s = fmaf(kk[j], qq[j], c0s);        c1s = fmaf(kk[j + 4], qq[j + 4], c1s);
            c2s = fmaf(kk[j + 8], qq[j + 8], c2s); c3s = fmaf(kk[j + 12], qq[j + 12], c3s);
        }
        float a = (a0 + a1) + (a2 + a3);
        float b = (b0 + b1) + (b2 + b3);
        float c = (c0s + c1s) + (c2s + c3s);

        a += __shfl_xor_sync(0xffffffffu, a, 1);
        b += __shfl_xor_sync(0xffffffffu, b, 1);
        c += __shfl_xor_sync(0xffffffffu, c, 1);
        a += __shfl_xor_sync(0xffffffffu, a, 2);
        b += __shfl_xor_sync(0xffffffffu, b, 2);
        c += __shfl_xor_sync(0xffffffffu, c, 2);

        float coef = bt * (a - vt);
        float ot = b - coef * c;
        #pragma unroll
        for (int j = 0; j < 16; j++) S[j] = fmaf(-coef, kk[j], S[j]);
        if (sub == 0) op[t * HID] = ot;

        #pragma unroll
        for (int j = 0; j < 16; j++) { kk[j] = nk[j]; qq[j] = nq[j]; }
        vt = nvt; bt = nbt;
        kp += HID; qp += HID; vp += HID; bp += NH;
    }

    #pragma unroll
    for (int j = 0; j < 16; j++)
        Sout[head * HD * HD + row * HD + c0 + j] = S[j];
}

// ---------------- SwiGLU elementwise -> fp16 ----------------
__global__ void swiglu_k(const float* __restrict__ g, const float* __restrict__ u,
                         f16* __restrict__ oh, int n) {
    int i = blockIdx.x * blockDim.x + threadIdx.x;
    if (i < n) {
        float x = g[i];
        float y = (x / (1.f + expf(-x))) * u[i];
        oh[i] = __float2half_rn(y);
    }
}

// ---------------- launch ----------------
extern "C" void kernel_launch(void* const* d_in, const int* in_sizes, int n_in,
                              void* d_out, int out_size) {
    const float* x_in   = (const float*)d_in[0];
    const float* attn_w = (const float*)d_in[1];
    const float* Wq     = (const float*)d_in[2];
    const float* Wk     = (const float*)d_in[3];
    const float* Wv     = (const float*)d_in[4];
    const float* cq     = (const float*)d_in[5];
    const float* ck     = (const float*)d_in[6];
    const float* cv     = (const float*)d_in[7];
    const float* Wb     = (const float*)d_in[8];
    const float* out_w  = (const float*)d_in[9];
    const float* Wout   = (const float*)d_in[10];
    const float* mlp_w  = (const float*)d_in[11];
    const float* Wg     = (const float*)d_in[12];
    const float* Wu     = (const float*)d_in[13];
    const float* Wd     = (const float*)d_in[14];

    float *h, *qr, *kr, *vr, *q, *k, *v, *beta, *o, *x1, *gate, *up, *Ssc;
    cudaGetSymbolAddress((void**)&h,   g_h);
    cudaGetSymbolAddress((void**)&qr,  g_qr);
    cudaGetSymbolAddress((void**)&kr,  g_kr);
    cudaGetSymbolAddress((void**)&vr,  g_vr);
    cudaGetSymbolAddress((void**)&q,   g_q);
    cudaGetSymbolAddress((void**)&k,   g_k);
    cudaGetSymbolAddress((void**)&v,   g_v);
    cudaGetSymbolAddress((void**)&beta,g_beta);
    cudaGetSymbolAddress((void**)&o,   g_o);
    cudaGetSymbolAddress((void**)&x1,  g_x1);
    cudaGetSymbolAddress((void**)&gate,g_gate);
    cudaGetSymbolAddress((void**)&up,  g_up);
    cudaGetSymbolAddress((void**)&Ssc, g_Ssc);

    f16 *hh, *onh, *h2h, *acth, *wq, *wk, *wv, *wo, *wg, *wu, *wd;
    cudaGetSymbolAddress((void**)&hh,   g_hh);
    cudaGetSymbolAddress((void**)&onh,  g_onh);
    cudaGetSymbolAddress((void**)&h2h,  g_h2h);
    cudaGetSymbolAddress((void**)&acth, g_acth);
    cudaGetSymbolAddress((void**)&wq, g_wq); cudaGetSymbolAddress((void**)&wk, g_wk);
    cudaGetSymbolAddress((void**)&wv, g_wv); cudaGetSymbolAddress((void**)&wo, g_wo);
    cudaGetSymbolAddress((void**)&wg, g_wg); cudaGetSymbolAddress((void**)&wu, g_wu);
    cudaGetSymbolAddress((void**)&wd, g_wd);

    float* out_x = (float*)d_out;
    float* Sdst = (out_size >= TT * HID + NH * HD * HD) ? (out_x + TT * HID) : Ssc;

    cudaFuncSetAttribute(mgemm<0>, cudaFuncAttributeMaxDynamicSharedMemorySize, SMEM_TOT);
    cudaFuncSetAttribute(mgemm<1>, cudaFuncAttributeMaxDynamicSharedMemorySize, SMEM_TOT);

    // ---- convert weights to fp16 (one batched pass) ----
    {
        C7 cp;
        cp.s[0] = Wq;   cp.d[0] = wq; cp.n4[0] = HID * HID / 4;
        cp.s[1] = Wk;   cp.d[1] = wk; cp.n4[1] = HID * HID / 4;
        cp.s[2] = Wv;   cp.d[2] = wv; cp.n4[2] = HID * HID / 4;
        cp.s[3] = Wout; cp.d[3] = wo; cp.n4[3] = HID * HID / 4;
        cp.s[4] = Wg;   cp.d[4] = wg; cp.n4[4] = INTER * HID / 4;
        cp.s[5] = Wu;   cp.d[5] = wu; cp.n4[5] = INTER * HID / 4;
        cp.s[6] = Wd;   cp.d[6] = wd; cp.n4[6] = HID * INTER / 4;
        dim3 g((INTER * HID / 4 + 255) / 256, 7);
        cvt7_k<<<g, 256>>>(cp);
    }

    // ---- attention sub-block ----
    rmsnorm_k<<<TT, 256>>>(x_in, attn_w, h, hh);

    {   // fused q/k/v projection
        GP p;
        p.B[0] = wq; p.C[0] = qr; p.R[0] = nullptr;
        p.B[1] = wk; p.C[1] = kr; p.R[1] = nullptr;
        p.B[2] = wv; p.C[2] = vr; p.R[2] = nullptr;
        dim3 g(HID / 128, TT / 128, 3);
        mgemm<0><<<g, 256, SMEM_TOT>>>(hh, p, TT, HID, HID);
    }

    {   // fused conv + double-silu for q/k/v
        CP3 cp = {{qr, kr, vr}, {cq, ck, cv}, {q, k, v}};
        dim3 g((TT * HID) / 256, 3);
        conv_silu2_k<<<g, 256>>>(cp);
    }

    l2norm_k<<<dim3(TT, 2), 1024>>>(q, k);
    beta_k<<<TT, 1024>>>(h, Wb, beta);

    delta_scan_k<<<64, 128>>>(k, q, v, beta, o, Sdst);

    rmsnorm_k<<<TT, 256>>>(o, out_w, nullptr, onh);
    {   // output projection + residual
        GP p;
        p.B[0] = wo; p.C[0] = x1; p.R[0] = x_in;
        p.B[1] = nullptr; p.C[1] = nullptr; p.R[1] = nullptr;
        p.B[2] = nullptr; p.C[2] = nullptr; p.R[2] = nullptr;
        dim3 g(HID / 128, TT / 128, 1);
        mgemm<1><<<g, 256, SMEM_TOT>>>(onh, p, TT, HID, HID);
    }

    // ---- MLP sub-block ----
    rmsnorm_k<<<TT, 256>>>(x1, mlp_w, nullptr, h2h);
    {   // fused gate + up projection
        GP p;
        p.B[0] = wg; p.C[0] = gate; p.R[0] = nullptr;
        p.B[1] = wu; p.C[1] = up;   p.R[1] = nullptr;
        p.B[2] = nullptr; p.C[2] = nullptr; p.R[2] = nullptr;
        dim3 g(INTER / 128, TT / 128, 2);
        mgemm<0><<<g, 256, SMEM_TOT>>>(h2h, p, TT, INTER, HID);
    }
    swiglu_k<<<(TT * INTER) / 256, 256>>>(gate, up, acth, TT * INTER);
    {   // down projection + residual
        GP p;
        p.B[0] = wd; p.C[0] = out_x; p.R[0] = x1;
        p.B[1] = nullptr; p.C[1] = nullptr; p.R[1] = nullptr;
        p.B[2] = nullptr; p.C[2] = nullptr; p.R[2] = nullptr;
        dim3 g(HID / 128, TT / 128, 1);
        mgemm<1><<<g, 256, SMEM_TOT>>>(acth, p, TT, HID, INTER);
    }
}

// round 12
// speedup vs baseline: 1.2163x; 1.0131x over previous
#include <cuda_runtime.h>
#include <cuda_fp16.h>
#include <math.h>
#include <stdint.h>

#define HID 2048
#define TT 1024
#define NH 32
#define HD 64
#define INTER 5632

typedef __half f16;

// ---------------- scratch (no allocations allowed) ----------------
__device__ float g_h[TT*HID];
__device__ float g_qr[TT*HID];
__device__ float g_kr[TT*HID];
__device__ float g_vr[TT*HID];
__device__ float g_q[TT*HID];
__device__ float g_k[TT*HID];
__device__ float g_v[TT*HID];
__device__ float g_beta[TT*NH];
__device__ float g_o[TT*HID];
__device__ float g_x1[TT*HID];
__device__ float g_gate[TT*INTER];
__device__ float g_Ssc[NH*HD*HD];

// fp16 operand buffers
__device__ f16 g_hh[TT*HID];       // rmsnorm(x) fp16
__device__ f16 g_onh[TT*HID];      // rmsnorm(o) fp16
__device__ f16 g_h2h[TT*HID];      // rmsnorm(x1) fp16
__device__ f16 g_acth[TT*INTER];   // swiglu fp16
__device__ f16 g_wq[HID*HID], g_wk[HID*HID], g_wv[HID*HID], g_wo[HID*HID];
__device__ f16 g_wg[INTER*HID], g_wu[INTER*HID], g_wd[HID*INTER];

// ================= helpers =================
__device__ __forceinline__ uint32_t smem_u32(const void* p) {
    uint32_t a;
    asm("{ .reg .u64 t; cvta.to.shared.u64 t, %1; cvt.u32.u64 %0, t; }" : "=r"(a) : "l"(p));
    return a;
}
__device__ __forceinline__ void ldmx4(uint32_t& r0, uint32_t& r1, uint32_t& r2, uint32_t& r3,
                                      uint32_t addr) {
    asm volatile("ldmatrix.sync.aligned.m8n8.x4.shared.b16 {%0,%1,%2,%3}, [%4];"
                 : "=r"(r0), "=r"(r1), "=r"(r2), "=r"(r3) : "r"(addr));
}
__device__ __forceinline__ void mma16816(float* c, const uint32_t* a, const uint32_t* b) {
    asm volatile(
        "mma.sync.aligned.m16n8k16.row.col.f32.f16.f16.f32 "
        "{%0,%1,%2,%3}, {%4,%5,%6,%7}, {%8,%9}, {%0,%1,%2,%3};"
        : "+f"(c[0]), "+f"(c[1]), "+f"(c[2]), "+f"(c[3])
        : "r"(a[0]), "r"(a[1]), "r"(a[2]), "r"(a[3]), "r"(b[0]), "r"(b[1]));
}
__device__ __forceinline__ void cpasync16(uint32_t saddr, const void* gptr) {
    asm volatile("cp.async.ca.shared.global [%0], [%1], 16;" :: "r"(saddr), "l"(gptr));
}
#define CP_COMMIT() asm volatile("cp.async.commit_group;" ::: "memory")
__device__ __forceinline__ void cp_wait(int pend) {
    if (pend <= 0)      asm volatile("cp.async.wait_group 0;" ::: "memory");
    else if (pend == 1) asm volatile("cp.async.wait_group 1;" ::: "memory");
    else                asm volatile("cp.async.wait_group 2;" ::: "memory");
}

// ================= fp16 tensor GEMM: C[M,N] = A[M,K] @ B[N,K]^T =================
// MODE 0: plain fp32 out.  MODE 1: + fp32 residual.  MODE 2: swiglu epilogue:
//   out_f16 = silu(G) * acc  (G = partner fp32 matrix, same shape).
#define BK 64
#define PADW 72
#define TILE_B (128 * PADW * 2)
#define STAGE_BYTES (2 * TILE_B)
#define NSTAGE 4
#define SMEM_TOT (NSTAGE * STAGE_BYTES)  // 147456 B

struct GP {
    const f16* B[3];
    float* C[3];
    const float* R[3];
    f16* Ch[3];
    const float* G[3];
};

template <int MODE>
__global__ void __launch_bounds__(256, 1)
mgemm(const f16* __restrict__ A, GP p, int M, int N, int K) {
    extern __shared__ char dsm[];
    const f16* __restrict__ B = p.B[blockIdx.z];

    const int tid = threadIdx.x;
    const int lane = tid & 31;
    const int wid = tid >> 5;
    const int wm = wid & 1;
    const int wn = wid >> 1;
    const int row0 = blockIdx.y * 128, col0 = blockIdx.x * 128;

    const f16* At = A + (size_t)row0 * K;
    const f16* Bt = B + (size_t)col0 * K;

    int rw[4], cl[4], soff[4];
    #pragma unroll
    for (int i = 0; i < 4; i++) {
        int t = i * 256 + tid;
        rw[i] = t >> 3;
        cl[i] = (t & 7) * 8;
        soff[i] = (rw[i] * PADW + cl[i]) * 2;
    }
    const uint32_t smem_base = smem_u32(dsm);

    float acc[4][4][4];
    #pragma unroll
    for (int mt = 0; mt < 4; mt++)
        #pragma unroll
        for (int nt = 0; nt < 4; nt++)
            #pragma unroll
            for (int j = 0; j < 4; j++) acc[mt][nt][j] = 0.f;

    const int aRow = wm * 64 + (lane & 15);
    const int aCol = (lane >> 4) * 8;
    const int bRow = wn * 32 + (lane >> 4) * 8 + (lane & 7);
    const int bCol = ((lane >> 3) & 1) * 8;

    const int nchunk = K / BK;

    auto issue = [&](int c) {
        uint32_t sb = smem_base + (c & (NSTAGE - 1)) * STAGE_BYTES;
        int gco = c * BK;
        #pragma unroll
        for (int i = 0; i < 4; i++) {
            size_t go = (size_t)rw[i] * K + gco + cl[i];
            cpasync16(sb + soff[i],          At + go);
            cpasync16(sb + TILE_B + soff[i], Bt + go);
        }
    };

    issue(0); CP_COMMIT();
    issue(1); CP_COMMIT();
    issue(2); CP_COMMIT();

    for (int c = 0; c < nchunk; c++) {
        int pend = nchunk - c - 1; if (pend > 2) pend = 2;
        cp_wait(pend);
        __syncthreads();
        if (c + 3 < nchunk) { issue(c + 3); CP_COMMIT(); }

        const uint32_t sbase = smem_base + (c & (NSTAGE - 1)) * STAGE_BYTES;
        const uint32_t aH = sbase;
        const uint32_t bH = sbase + TILE_B;

        #pragma unroll
        for (int kt = 0; kt < 4; kt++) {
            uint32_t ah[4][4], bh[4][2];
            #pragma unroll
            for (int mt = 0; mt < 4; mt++) {
                uint32_t off = ((uint32_t)(aRow + mt * 16) * PADW + aCol + kt * 16) * 2;
                ldmx4(ah[mt][0], ah[mt][1], ah[mt][2], ah[mt][3], aH + off);
            }
            #pragma unroll
            for (int n2 = 0; n2 < 2; n2++) {
                uint32_t off = ((uint32_t)(bRow + n2 * 16) * PADW + bCol + kt * 16) * 2;
                uint32_t r0, r1, r2, r3;
                ldmx4(r0, r1, r2, r3, bH + off);
                bh[n2 * 2][0] = r0;     bh[n2 * 2][1] = r1;
                bh[n2 * 2 + 1][0] = r2; bh[n2 * 2 + 1][1] = r3;
            }
            #pragma unroll
            for (int mt = 0; mt < 4; mt++)
                #pragma unroll
                for (int nt = 0; nt < 4; nt++)
                    mma16816(acc[mt][nt], ah[mt], bh[nt]);
        }
    }

    if (MODE == 2) {
        f16* __restrict__ Ch = p.Ch[blockIdx.z];
        const float* __restrict__ Gp = p.G[blockIdx.z];
        #pragma unroll
        for (int mt = 0; mt < 4; mt++) {
            int r0g = row0 + wm * 64 + mt * 16 + (lane >> 2);
            #pragma unroll
            for (int nt = 0; nt < 4; nt++) {
                int cg = col0 + wn * 32 + nt * 8 + (lane & 3) * 2;
                #pragma unroll
                for (int half = 0; half < 2; half++) {
                    int rr2 = r0g + half * 8;
                    size_t idx = (size_t)rr2 * N + cg;
                    float g0 = Gp[idx], g1 = Gp[idx + 1];
                    float u0 = acc[mt][nt][half * 2], u1 = acc[mt][nt][half * 2 + 1];
                    float y0 = (g0 / (1.f + expf(-g0))) * u0;
                    float y1 = (g1 / (1.f + expf(-g1))) * u1;
                    __half2 hv = __floats2half2_rn(y0, y1);
                    *(__half2*)(Ch + idx) = hv;
                }
            }
        }
    } else {
        float* __restrict__ C = p.C[blockIdx.z];
        const float* __restrict__ Rsd = (MODE == 1) ? p.R[blockIdx.z] : nullptr;
        #pragma unroll
        for (int mt = 0; mt < 4; mt++) {
            int r0g = row0 + wm * 64 + mt * 16 + (lane >> 2);
            #pragma unroll
            for (int nt = 0; nt < 4; nt++) {
                int cg = col0 + wn * 32 + nt * 8 + (lane & 3) * 2;
                float2 v0 = make_float2(acc[mt][nt][0], acc[mt][nt][1]);
                float2 v1 = make_float2(acc[mt][nt][2], acc[mt][nt][3]);
                if (MODE == 1) {
                    float2 q0 = *(const float2*)(Rsd + (size_t)r0g * N + cg);
                    float2 q1 = *(const float2*)(Rsd + (size_t)(r0g + 8) * N + cg);
                    v0.x += q0.x; v0.y += q0.y;
                    v1.x += q1.x; v1.y += q1.y;
                }
                *(float2*)(C + (size_t)r0g * N + cg) = v0;
                *(float2*)(C + (size_t)(r0g + 8) * N + cg) = v1;
            }
        }
    }
}

// ---------------- batched fp32 -> fp16 weight converter ----------------
struct C7 {
    const float* s[7];
    f16* d[7];
    int n4[7];
};
__global__ void cvt7_k(C7 p) {
    int z = blockIdx.y;
    int i4 = blockIdx.x * 256 + threadIdx.x;
    if (i4 >= p.n4[z]) return;
    float4 v = ((const float4*)p.s[z])[i4];
    __half2 h0 = __floats2half2_rn(v.x, v.y);
    __half2 h1 = __floats2half2_rn(v.z, v.w);
    ((uint2*)p.d[z])[i4] = make_uint2(*(uint32_t*)&h0, *(uint32_t*)&h1);
}

// ---------------- RMSNorm (fp32 optional + fp16 out) ----------------
__global__ void rmsnorm_k(const float* __restrict__ x, const float* __restrict__ w,
                          float* __restrict__ out, f16* __restrict__ oh) {
    int row = blockIdx.x;
    const float* xr = x + row * HID;
    float ss = 0.f;
    for (int i = threadIdx.x; i < HID; i += 256) { float v = xr[i]; ss += v * v; }
    #pragma unroll
    for (int m = 16; m; m >>= 1) ss += __shfl_xor_sync(0xffffffffu, ss, m);
    __shared__ float red[8];
    if ((threadIdx.x & 31) == 0) red[threadIdx.x >> 5] = ss;
    __syncthreads();
    if (threadIdx.x < 8) {
        float r = red[threadIdx.x];
        #pragma unroll
        for (int m = 4; m; m >>= 1) r += __shfl_xor_sync(0xffu, r, m);
        if (threadIdx.x == 0) red[0] = r;
    }
    __syncthreads();
    float scale = rsqrtf(red[0] * (1.0f / (float)HID) + 1e-6f);
    for (int i = threadIdx.x; i < HID; i += 256) {
        float y = xr[i] * scale * w[i];
        if (out) out[row * HID + i] = y;
        oh[row * HID + i] = __float2half_rn(y);
    }
}

// ---------------- sliding-window causal dwconv (K=4) + silu(silu(.)), 3 streams ----------------
// Each thread: one channel c, 8 consecutive timesteps. Loads 11 rows instead of 32.
#define CT 8
struct CP3 { const float* in[3]; const float* w[3]; float* out[3]; };

__global__ void conv_sw_k(CP3 p) {
    int z = blockIdx.y;
    const float* __restrict__ in = p.in[z];
    float* __restrict__ out = p.out[z];

    int bx = blockIdx.x;                       // 0 .. (HID/256)*(TT/CT)-1
    int c  = (bx & 7) * 256 + threadIdx.x;     // HID/256 == 8
    int t0 = (bx >> 3) * CT;

    float4 wv = *(const float4*)(p.w[z] + c * 4);
    float wc[4] = {wv.x, wv.y, wv.z, wv.w};

    float xv[CT + 3];
    #pragma unroll
    for (int j = 0; j < 3; j++) {
        int ti = t0 - 3 + j;
        xv[j] = (ti >= 0) ? in[(size_t)ti * HID + c] : 0.f;
    }
    #pragma unroll
    for (int j = 0; j < CT; j++)
        xv[3 + j] = in[(size_t)(t0 + j) * HID + c];

    #pragma unroll
    for (int i = 0; i < CT; i++) {
        float acc = 0.f;
        #pragma unroll
        for (int j = 0; j < 4; j++)
            acc = fmaf(xv[i + j], wc[j], acc);
        float s1 = acc / (1.f + expf(-acc));
        float s2 = s1 / (1.f + expf(-s1));
        out[(size_t)(t0 + i) * HID + c] = s2;
    }
}

// ---------------- merged l2norm(q), l2norm(k), beta ----------------
__global__ void l2beta_k(float* __restrict__ pq, float* __restrict__ pk,
                         const float* __restrict__ hbuf, const float* __restrict__ Wb,
                         float* __restrict__ beta) {
    int t = blockIdx.x;
    int y = blockIdx.y;
    int h = threadIdx.x >> 5, l = threadIdx.x & 31;
    if (y < 2) {
        float* r = (y ? pk : pq) + t * HID + h * HD;
        float a = r[l], b = r[l + 32];
        float ss = a * a + b * b;
        #pragma unroll
        for (int m = 16; m; m >>= 1) ss += __shfl_xor_sync(0xffffffffu, ss, m);
        float inv = 1.f / fmaxf(sqrtf(ss), 1e-12f);
        r[l] = a * inv;
        r[l + 32] = b * inv;
    } else {
        const float* hr = hbuf + t * HID;
        const float* wr = Wb + h * HID;
        float s = 0.f;
        for (int i = l; i < HID; i += 32) s = fmaf(hr[i], wr[i], s);
        #pragma unroll
        for (int m = 16; m; m >>= 1) s += __shfl_xor_sync(0xffffffffu, s, m);
        if (l == 0) beta[t * NH + h] = 1.f / (1.f + expf(-s));
    }
}

// ---------------- delta scan (4-chain dots + next-step prefetch) ----------------
__global__ void delta_scan_k(const float* __restrict__ kb, const float* __restrict__ qb,
                             const float* __restrict__ vb, const float* __restrict__ betab,
                             float* __restrict__ ob, float* __restrict__ Sout) {
    int gtid = blockIdx.x * blockDim.x + threadIdx.x;
    int sub  = gtid & 3;
    int task = gtid >> 2;
    int head = task >> 6;
    int row  = task & 63;
    int c0   = sub << 4;

    float S[16];
    #pragma unroll
    for (int j = 0; j < 16; j++) S[j] = 0.f;

    const float* kp = kb + head * HD + c0;
    const float* qp = qb + head * HD + c0;
    const float* vp = vb + head * HD + row;
    const float* bp = betab + head;
    float* op = ob + head * HD + row;

    float kk[16], qq[16], vt, bt;
    #pragma unroll
    for (int j = 0; j < 16; j += 4) {
        *(float4*)(kk + j) = *(const float4*)(kp + j);
        *(float4*)(qq + j) = *(const float4*)(qp + j);
    }
    vt = *vp; bt = *bp;

    for (int t = 0; t < TT; t++) {
        float nk[16], nq[16], nvt = 0.f, nbt = 0.f;
        if (t + 1 < TT) {
            const float* kp1 = kp + HID;
            const float* qp1 = qp + HID;
            #pragma unroll
            for (int j = 0; j < 16; j += 4) {
                *(float4*)(nk + j) = *(const float4*)(kp1 + j);
                *(float4*)(nq + j) = *(const float4*)(qp1 + j);
            }
            nvt = vp[HID]; nbt = bp[NH];
        }

        float a0 = 0.f, a1 = 0.f, a2 = 0.f, a3 = 0.f;
        float b0 = 0.f, b1 = 0.f, b2 = 0.f, b3 = 0.f;
        float c0s = 0.f, c1s = 0.f, c2s = 0.f, c3s = 0.f;
        #pragma unroll
        for (int j = 0; j < 4; j++) {
            a0 = fmaf(S[j], kk[j], a0);           a1 = fmaf(S[j + 4], kk[j + 4], a1);
            a2 = fmaf(S[j + 8], kk[j + 8], a2);   a3 = fmaf(S[j + 12], kk[j + 12], a3);
            b0 = fmaf(S[j], qq[j], b0);           b1 = fmaf(S[j + 4], qq[j + 4], b1);
            b2 = fmaf(S[j + 8], qq[j + 8], b2);   b3 = fmaf(S[j + 12], qq[j + 12], b3);
            c0s = fmaf(kk[j], qq[j], c0s);        c1s = fmaf(kk[j + 4], qq[j + 4], c1s);
            c2s = fmaf(kk[j + 8], qq[j + 8], c2s); c3s = fmaf(kk[j + 12], qq[j + 12], c3s);
        }
        float a = (a0 + a1) + (a2 + a3);
        float b = (b0 + b1) + (b2 + b3);
        float c = (c0s + c1s) + (c2s + c3s);

        a += __shfl_xor_sync(0xffffffffu, a, 1);
        b += __shfl_xor_sync(0xffffffffu, b, 1);
        c += __shfl_xor_sync(0xffffffffu, c, 1);
        a += __shfl_xor_sync(0xffffffffu, a, 2);
        b += __shfl_xor_sync(0xffffffffu, b, 2);
        c += __shfl_xor_sync(0xffffffffu, c, 2);

        float coef = bt * (a - vt);
        float ot = b - coef * c;
        #pragma unroll
        for (int j = 0; j < 16; j++) S[j] = fmaf(-coef, kk[j], S[j]);
        if (sub == 0) op[t * HID] = ot;

        #pragma unroll
        for (int j = 0; j < 16; j++) { kk[j] = nk[j]; qq[j] = nq[j]; }
        vt = nvt; bt = nbt;
        kp += HID; qp += HID; vp += HID; bp += NH;
    }

    #pragma unroll
    for (int j = 0; j < 16; j++)
        Sout[head * HD * HD + row * HD + c0 + j] = S[j];
}

// ---------------- launch ----------------
extern "C" void kernel_launch(void* const* d_in, const int* in_sizes, int n_in,
                              void* d_out, int out_size) {
    const float* x_in   = (const float*)d_in[0];
    const float* attn_w = (const float*)d_in[1];
    const float* Wq     = (const float*)d_in[2];
    const float* Wk     = (const float*)d_in[3];
    const float* Wv     = (const float*)d_in[4];
    const float* cq     = (const float*)d_in[5];
    const float* ck     = (const float*)d_in[6];
    const float* cv     = (const float*)d_in[7];
    const float* Wb     = (const float*)d_in[8];
    const float* out_w  = (const float*)d_in[9];
    const float* Wout   = (const float*)d_in[10];
    const float* mlp_w  = (const float*)d_in[11];
    const float* Wg     = (const float*)d_in[12];
    const float* Wu     = (const float*)d_in[13];
    const float* Wd     = (const float*)d_in[14];

    float *h, *qr, *kr, *vr, *q, *k, *v, *beta, *o, *x1, *gate, *Ssc;
    cudaGetSymbolAddress((void**)&h,   g_h);
    cudaGetSymbolAddress((void**)&qr,  g_qr);
    cudaGetSymbolAddress((void**)&kr,  g_kr);
    cudaGetSymbolAddress((void**)&vr,  g_vr);
    cudaGetSymbolAddress((void**)&q,   g_q);
    cudaGetSymbolAddress((void**)&k,   g_k);
    cudaGetSymbolAddress((void**)&v,   g_v);
    cudaGetSymbolAddress((void**)&beta,g_beta);
    cudaGetSymbolAddress((void**)&o,   g_o);
    cudaGetSymbolAddress((void**)&x1,  g_x1);
    cudaGetSymbolAddress((void**)&gate,g_gate);
    cudaGetSymbolAddress((void**)&Ssc, g_Ssc);

    f16 *hh, *onh, *h2h, *acth, *wq, *wk, *wv, *wo, *wg, *wu, *wd;
    cudaGetSymbolAddress((void**)&hh,   g_hh);
    cudaGetSymbolAddress((void**)&onh,  g_onh);
    cudaGetSymbolAddress((void**)&h2h,  g_h2h);
    cudaGetSymbolAddress((void**)&acth, g_acth);
    cudaGetSymbolAddress((void**)&wq, g_wq); cudaGetSymbolAddress((void**)&wk, g_wk);
    cudaGetSymbolAddress((void**)&wv, g_wv); cudaGetSymbolAddress((void**)&wo, g_wo);
    cudaGetSymbolAddress((void**)&wg, g_wg); cudaGetSymbolAddress((void**)&wu, g_wu);
    cudaGetSymbolAddress((void**)&wd, g_wd);

    float* out_x = (float*)d_out;
    float* Sdst = (out_size >= TT * HID + NH * HD * HD) ? (out_x + TT * HID) : Ssc;

    cudaFuncSetAttribute(mgemm<0>, cudaFuncAttributeMaxDynamicSharedMemorySize, SMEM_TOT);
    cudaFuncSetAttribute(mgemm<1>, cudaFuncAttributeMaxDynamicSharedMemorySize, SMEM_TOT);
    cudaFuncSetAttribute(mgemm<2>, cudaFuncAttributeMaxDynamicSharedMemorySize, SMEM_TOT);

    // ---- convert weights to fp16 (one batched pass) ----
    {
        C7 cp;
        cp.s[0] = Wq;   cp.d[0] = wq; cp.n4[0] = HID * HID / 4;
        cp.s[1] = Wk;   cp.d[1] = wk; cp.n4[1] = HID * HID / 4;
        cp.s[2] = Wv;   cp.d[2] = wv; cp.n4[2] = HID * HID / 4;
        cp.s[3] = Wout; cp.d[3] = wo; cp.n4[3] = HID * HID / 4;
        cp.s[4] = Wg;   cp.d[4] = wg; cp.n4[4] = INTER * HID / 4;
        cp.s[5] = Wu;   cp.d[5] = wu; cp.n4[5] = INTER * HID / 4;
        cp.s[6] = Wd;   cp.d[6] = wd; cp.n4[6] = HID * INTER / 4;
        dim3 g((INTER * HID / 4 + 255) / 256, 7);
        cvt7_k<<<g, 256>>>(cp);
    }

    GP z0 = {};

    // ---- attention sub-block ----
    rmsnorm_k<<<TT, 256>>>(x_in, attn_w, h, hh);

    {   // fused q/k/v projection
        GP p = z0;
        p.B[0] = wq; p.C[0] = qr;
        p.B[1] = wk; p.C[1] = kr;
        p.B[2] = wv; p.C[2] = vr;
        dim3 g(HID / 128, TT / 128, 3);
        mgemm<0><<<g, 256, SMEM_TOT>>>(hh, p, TT, HID, HID);
    }

    {   // sliding-window conv + double-silu for q/k/v
        CP3 cp = {{qr, kr, vr}, {cq, ck, cv}, {q, k, v}};
        dim3 g((HID / 256) * (TT / CT), 3);
        conv_sw_k<<<g, 256>>>(cp);
    }

    l2beta_k<<<dim3(TT, 3), 1024>>>(q, k, h, Wb, beta);

    delta_scan_k<<<64, 128>>>(k, q, v, beta, o, Sdst);

    rmsnorm_k<<<TT, 256>>>(o, out_w, nullptr, onh);
    {   // output projection + residual
        GP p = z0;
        p.B[0] = wo; p.C[0] = x1; p.R[0] = x_in;
        dim3 g(HID / 128, TT / 128, 1);
        mgemm<1><<<g, 256, SMEM_TOT>>>(onh, p, TT, HID, HID);
    }

    // ---- MLP sub-block ----
    rmsnorm_k<<<TT, 256>>>(x1, mlp_w, nullptr, h2h);
    {   // gate projection (fp32)
        GP p = z0;
        p.B[0] = wg; p.C[0] = gate;
        dim3 g(INTER / 128, TT / 128, 1);
        mgemm<0><<<g, 256, SMEM_TOT>>>(h2h, p, TT, INTER, HID);
    }
    {   // up projection with fused swiglu epilogue -> acth fp16
        GP p = z0;
        p.B[0] = wu; p.Ch[0] = acth; p.G[0] = gate;
        dim3 g(INTER / 128, TT / 128, 1);
        mgemm<2><<<g, 256, SMEM_TOT>>>(h2h, p, TT, INTER, HID);
    }
    {   // down projection + residual
        GP p = z0;
        p.B[0] = wd; p.C[0] = out_x; p.R[0] = x1;
        dim3 g(HID / 128, TT / 128, 1);
        mgemm<1><<<g, 256, SMEM_TOT>>>(acth, p, TT, HID, INTER);
    }
}

// round 13
// speedup vs baseline: 1.8352x; 1.5088x over previous
#include <cuda_runtime.h>
#include <cuda_fp16.h>
#include <math.h>
#include <stdint.h>

#define HID 2048
#define TT 1024
#define NH 32
#define HD 64
#define INTER 5632

typedef __half f16;

// ---------------- scratch (no allocations allowed) ----------------
__device__ float g_h[TT*HID];
__device__ float g_qr[TT*HID];
__device__ float g_kr[TT*HID];
__device__ float g_vr[TT*HID];
__device__ float g_q[TT*HID];
__device__ float g_k[TT*HID];
__device__ float g_v[TT*HID];
__device__ float g_beta[TT*NH];
__device__ float g_o[TT*HID];
__device__ float g_x1[TT*HID];
__device__ float g_Ssc[NH*HD*HD];

// fp16 operand buffers
__device__ f16 g_hh[TT*HID];
__device__ f16 g_onh[TT*HID];
__device__ f16 g_h2h[TT*HID];
__device__ f16 g_acth[TT*INTER];
__device__ f16 g_wq[HID*HID], g_wk[HID*HID], g_wv[HID*HID], g_wo[HID*HID];
__device__ f16 g_wg[INTER*HID], g_wu[INTER*HID], g_wd[HID*INTER];

// ================= helpers =================
__device__ __forceinline__ uint32_t smem_u32(const void* p) {
    uint32_t a;
    asm("{ .reg .u64 t; cvta.to.shared.u64 t, %1; cvt.u32.u64 %0, t; }" : "=r"(a) : "l"(p));
    return a;
}
__device__ __forceinline__ void ldmx4(uint32_t& r0, uint32_t& r1, uint32_t& r2, uint32_t& r3,
                                      uint32_t addr) {
    asm volatile("ldmatrix.sync.aligned.m8n8.x4.shared.b16 {%0,%1,%2,%3}, [%4];"
                 : "=r"(r0), "=r"(r1), "=r"(r2), "=r"(r3) : "r"(addr));
}
__device__ __forceinline__ void mma16816(float* c, const uint32_t* a, const uint32_t* b) {
    asm volatile(
        "mma.sync.aligned.m16n8k16.row.col.f32.f16.f16.f32 "
        "{%0,%1,%2,%3}, {%4,%5,%6,%7}, {%8,%9}, {%0,%1,%2,%3};"
        : "+f"(c[0]), "+f"(c[1]), "+f"(c[2]), "+f"(c[3])
        : "r"(a[0]), "r"(a[1]), "r"(a[2]), "r"(a[3]), "r"(b[0]), "r"(b[1]));
}
__device__ __forceinline__ void cpasync16(uint32_t saddr, const void* gptr) {
    asm volatile("cp.async.ca.shared.global [%0], [%1], 16;" :: "r"(saddr), "l"(gptr));
}
#define CP_COMMIT() asm volatile("cp.async.commit_group;" ::: "memory")
__device__ __forceinline__ void cp_wait(int pend) {
    if (pend <= 0)      asm volatile("cp.async.wait_group 0;" ::: "memory");
    else                asm volatile("cp.async.wait_group 1;" ::: "memory");
}

#define BK 64
#define PADW 72
#define A_TILE_B (128 * PADW * 2)      // 18432 B

// ================= fp16 tensor GEMM (128x128 tile, 3-stage, 2 CTA/SM) =================
#define G_STAGE (2 * A_TILE_B)         // A + B
#define G_SMEM (3 * G_STAGE)           // 110592 B

struct GP {
    const f16* B[3];
    float* C[3];
    const float* R[3];
};

template <int RES>
__global__ void __launch_bounds__(256, 2)
mgemm(const f16* __restrict__ A, GP p, int M, int N, int K) {
    extern __shared__ char dsm[];
    const f16* __restrict__ B = p.B[blockIdx.z];
    float* __restrict__ C = p.C[blockIdx.z];
    const float* __restrict__ Rsd = RES ? p.R[blockIdx.z] : nullptr;

    const int tid = threadIdx.x;
    const int lane = tid & 31;
    const int wid = tid >> 5;
    const int wm = wid & 1;
    const int wn = wid >> 1;
    const int row0 = blockIdx.y * 128, col0 = blockIdx.x * 128;

    const f16* At = A + (size_t)row0 * K;
    const f16* Bt = B + (size_t)col0 * K;

    int rw[4], cl[4], soff[4];
    #pragma unroll
    for (int i = 0; i < 4; i++) {
        int t = i * 256 + tid;
        rw[i] = t >> 3;
        cl[i] = (t & 7) * 8;
        soff[i] = (rw[i] * PADW + cl[i]) * 2;
    }
    const uint32_t smem_base = smem_u32(dsm);

    float acc[4][4][4];
    #pragma unroll
    for (int mt = 0; mt < 4; mt++)
        #pragma unroll
        for (int nt = 0; nt < 4; nt++)
            #pragma unroll
            for (int j = 0; j < 4; j++) acc[mt][nt][j] = 0.f;

    const int aRow = wm * 64 + (lane & 15);
    const int aCol = (lane >> 4) * 8;
    const int bRow = wn * 32 + (lane >> 4) * 8 + (lane & 7);
    const int bCol = ((lane >> 3) & 1) * 8;

    const int nchunk = K / BK;

    auto issue = [&](int c) {
        uint32_t sb = smem_base + (c % 3) * G_STAGE;
        int gco = c * BK;
        #pragma unroll
        for (int i = 0; i < 4; i++) {
            size_t go = (size_t)rw[i] * K + gco + cl[i];
            cpasync16(sb + soff[i],            At + go);
            cpasync16(sb + A_TILE_B + soff[i], Bt + go);
        }
    };

    issue(0); CP_COMMIT();
    issue(1); CP_COMMIT();

    for (int c = 0; c < nchunk; c++) {
        cp_wait(c + 1 < nchunk ? 1 : 0);
        __syncthreads();
        if (c + 2 < nchunk) { issue(c + 2); CP_COMMIT(); }

        const uint32_t sbase = smem_base + (c % 3) * G_STAGE;
        const uint32_t aH = sbase;
        const uint32_t bH = sbase + A_TILE_B;

        #pragma unroll
        for (int kt = 0; kt < 4; kt++) {
            uint32_t ah[4][4], bh[4][2];
            #pragma unroll
            for (int mt = 0; mt < 4; mt++) {
                uint32_t off = ((uint32_t)(aRow + mt * 16) * PADW + aCol + kt * 16) * 2;
                ldmx4(ah[mt][0], ah[mt][1], ah[mt][2], ah[mt][3], aH + off);
            }
            #pragma unroll
            for (int n2 = 0; n2 < 2; n2++) {
                uint32_t off = ((uint32_t)(bRow + n2 * 16) * PADW + bCol + kt * 16) * 2;
                uint32_t r0, r1, r2, r3;
                ldmx4(r0, r1, r2, r3, bH + off);
                bh[n2 * 2][0] = r0;     bh[n2 * 2][1] = r1;
                bh[n2 * 2 + 1][0] = r2; bh[n2 * 2 + 1][1] = r3;
            }
            #pragma unroll
            for (int mt = 0; mt < 4; mt++)
                #pragma unroll
                for (int nt = 0; nt < 4; nt++)
                    mma16816(acc[mt][nt], ah[mt], bh[nt]);
        }
    }

    #pragma unroll
    for (int mt = 0; mt < 4; mt++) {
        int r0g = row0 + wm * 64 + mt * 16 + (lane >> 2);
        #pragma unroll
        for (int nt = 0; nt < 4; nt++) {
            int cg = col0 + wn * 32 + nt * 8 + (lane & 3) * 2;
            float2 v0 = make_float2(acc[mt][nt][0], acc[mt][nt][1]);
            float2 v1 = make_float2(acc[mt][nt][2], acc[mt][nt][3]);
            if (RES) {
                float2 q0 = *(const float2*)(Rsd + (size_t)r0g * N + cg);
                float2 q1 = *(const float2*)(Rsd + (size_t)(r0g + 8) * N + cg);
                v0.x += q0.x; v0.y += q0.y;
                v1.x += q1.x; v1.y += q1.y;
            }
            *(float2*)(C + (size_t)r0g * N + cg) = v0;
            *(float2*)(C + (size_t)(r0g + 8) * N + cg) = v1;
        }
    }
}

// ================= fused gate+up+swiglu GEMM =================
// CTA tile: 128 rows x 64 cols of BOTH gate and up (two B tiles, shared A).
// Epilogue: acth = fp16( silu(acc_g) * acc_u ). No fp32 gate buffer.
#define B_TILE_B (64 * PADW * 2)            // 9216 B
#define GU_STAGE (A_TILE_B + 2 * B_TILE_B)  // 36864 B
#define GU_SMEM (3 * GU_STAGE)              // 110592 B

__global__ void __launch_bounds__(256, 2)
gateup_k(const f16* __restrict__ A, const f16* __restrict__ Bg,
         const f16* __restrict__ Bu, f16* __restrict__ Ch, int M, int N, int K) {
    extern __shared__ char dsm[];
    const int tid = threadIdx.x;
    const int lane = tid & 31;
    const int wid = tid >> 5;
    const int wm = wid & 1;        // 2 m-groups of 64
    const int wn = wid >> 1;       // 4 n-groups of 16
    const int row0 = blockIdx.y * 128, col0 = blockIdx.x * 64;

    const f16* At  = A  + (size_t)row0 * K;
    const f16* Bgt = Bg + (size_t)col0 * K;
    const f16* But = Bu + (size_t)col0 * K;

    // A: 128x64 fp16 -> 1024 16B chunks -> 4/thread.  B: 64x64 -> 512 -> 2/thread each.
    int arw[4], acl[4], asoff[4];
    #pragma unroll
    for (int i = 0; i < 4; i++) {
        int t = i * 256 + tid;
        arw[i] = t >> 3;
        acl[i] = (t & 7) * 8;
        asoff[i] = (arw[i] * PADW + acl[i]) * 2;
    }
    int brw[2], bcl[2], bsoff[2];
    #pragma unroll
    for (int i = 0; i < 2; i++) {
        int t = i * 256 + tid;
        brw[i] = t >> 3;
        bcl[i] = (t & 7) * 8;
        bsoff[i] = (brw[i] * PADW + bcl[i]) * 2;
    }
    const uint32_t smem_base = smem_u32(dsm);

    float ag[4][2][4], au[4][2][4];
    #pragma unroll
    for (int mt = 0; mt < 4; mt++)
        #pragma unroll
        for (int nt = 0; nt < 2; nt++)
            #pragma unroll
            for (int j = 0; j < 4; j++) { ag[mt][nt][j] = 0.f; au[mt][nt][j] = 0.f; }

    const int aRow = wm * 64 + (lane & 15);
    const int aCol = (lane >> 4) * 8;
    const int bRow = wn * 16 + (lane >> 4) * 8 + (lane & 7);
    const int bCol = ((lane >> 3) & 1) * 8;

    const int nchunk = K / BK;

    auto issue = [&](int c) {
        uint32_t sb = smem_base + (c % 3) * GU_STAGE;
        int gco = c * BK;
        #pragma unroll
        for (int i = 0; i < 4; i++)
            cpasync16(sb + asoff[i], At + (size_t)arw[i] * K + gco + acl[i]);
        #pragma unroll
        for (int i = 0; i < 2; i++) {
            size_t go = (size_t)brw[i] * K + gco + bcl[i];
            cpasync16(sb + A_TILE_B + bsoff[i],            Bgt + go);
            cpasync16(sb + A_TILE_B + B_TILE_B + bsoff[i], But + go);
        }
    };

    issue(0); CP_COMMIT();
    issue(1); CP_COMMIT();

    for (int c = 0; c < nchunk; c++) {
        cp_wait(c + 1 < nchunk ? 1 : 0);
        __syncthreads();
        if (c + 2 < nchunk) { issue(c + 2); CP_COMMIT(); }

        const uint32_t sbase = smem_base + (c % 3) * GU_STAGE;
        const uint32_t aH = sbase;
        const uint32_t gH = sbase + A_TILE_B;
        const uint32_t uH = sbase + A_TILE_B + B_TILE_B;

        #pragma unroll
        for (int kt = 0; kt < 4; kt++) {
            uint32_t ah[4][4], bg[2][2], bu[2][2];
            #pragma unroll
            for (int mt = 0; mt < 4; mt++) {
                uint32_t off = ((uint32_t)(aRow + mt * 16) * PADW + aCol + kt * 16) * 2;
                ldmx4(ah[mt][0], ah[mt][1], ah[mt][2], ah[mt][3], aH + off);
            }
            {
                uint32_t off = ((uint32_t)bRow * PADW + bCol + kt * 16) * 2;
                uint32_t r0, r1, r2, r3;
                ldmx4(r0, r1, r2, r3, gH + off);
                bg[0][0] = r0; bg[0][1] = r1; bg[1][0] = r2; bg[1][1] = r3;
                ldmx4(r0, r1, r2, r3, uH + off);
                bu[0][0] = r0; bu[0][1] = r1; bu[1][0] = r2; bu[1][1] = r3;
            }
            #pragma unroll
            for (int mt = 0; mt < 4; mt++)
                #pragma unroll
                for (int nt = 0; nt < 2; nt++) {
                    mma16816(ag[mt][nt], ah[mt], bg[nt]);
                    mma16816(au[mt][nt], ah[mt], bu[nt]);
                }
        }
    }

    #pragma unroll
    for (int mt = 0; mt < 4; mt++) {
        int r0g = row0 + wm * 64 + mt * 16 + (lane >> 2);
        #pragma unroll
        for (int nt = 0; nt < 2; nt++) {
            int cg = col0 + wn * 16 + nt * 8 + (lane & 3) * 2;
            #pragma unroll
            for (int half = 0; half < 2; half++) {
                int rr2 = r0g + half * 8;
                size_t idx = (size_t)rr2 * N + cg;
                float g0 = ag[mt][nt][half * 2], g1 = ag[mt][nt][half * 2 + 1];
                float u0 = au[mt][nt][half * 2], u1 = au[mt][nt][half * 2 + 1];
                float y0 = (g0 / (1.f + expf(-g0))) * u0;
                float y1 = (g1 / (1.f + expf(-g1))) * u1;
                __half2 hv = __floats2half2_rn(y0, y1);
                *(__half2*)(Ch + idx) = hv;
            }
        }
    }
}

// ---------------- batched fp32 -> fp16 weight converter ----------------
struct C7 {
    const float* s[7];
    f16* d[7];
    int n4[7];
};
__global__ void cvt7_k(C7 p) {
    int z = blockIdx.y;
    int i4 = blockIdx.x * 256 + threadIdx.x;
    if (i4 >= p.n4[z]) return;
    float4 v = ((const float4*)p.s[z])[i4];
    __half2 h0 = __floats2half2_rn(v.x, v.y);
    __half2 h1 = __floats2half2_rn(v.z, v.w);
    ((uint2*)p.d[z])[i4] = make_uint2(*(uint32_t*)&h0, *(uint32_t*)&h1);
}

// ---------------- RMSNorm (fp32 optional + fp16 out) ----------------
__global__ void rmsnorm_k(const float* __restrict__ x, const float* __restrict__ w,
                          float* __restrict__ out, f16* __restrict__ oh) {
    int row = blockIdx.x;
    const float* xr = x + row * HID;
    float ss = 0.f;
    for (int i = threadIdx.x; i < HID; i += 256) { float v = xr[i]; ss += v * v; }
    #pragma unroll
    for (int m = 16; m; m >>= 1) ss += __shfl_xor_sync(0xffffffffu, ss, m);
    __shared__ float red[8];
    if ((threadIdx.x & 31) == 0) red[threadIdx.x >> 5] = ss;
    __syncthreads();
    if (threadIdx.x < 8) {
        float r = red[threadIdx.x];
        #pragma unroll
        for (int m = 4; m; m >>= 1) r += __shfl_xor_sync(0xffu, r, m);
        if (threadIdx.x == 0) red[0] = r;
    }
    __syncthreads();
    float scale = rsqrtf(red[0] * (1.0f / (float)HID) + 1e-6f);
    for (int i = threadIdx.x; i < HID; i += 256) {
        float y = xr[i] * scale * w[i];
        if (out) out[row * HID + i] = y;
        oh[row * HID + i] = __float2half_rn(y);
    }
}

// ---------------- sliding-window causal dwconv (K=4) + silu(silu(.)) ----------------
#define CT 8
struct CP3 { const float* in[3]; const float* w[3]; float* out[3]; };

__global__ void conv_sw_k(CP3 p) {
    int z = blockIdx.y;
    const float* __restrict__ in = p.in[z];
    float* __restrict__ out = p.out[z];

    int bx = blockIdx.x;
    int c  = (bx & 7) * 256 + threadIdx.x;
    int t0 = (bx >> 3) * CT;

    float4 wv = *(const float4*)(p.w[z] + c * 4);
    float wc[4] = {wv.x, wv.y, wv.z, wv.w};

    float xv[CT + 3];
    #pragma unroll
    for (int j = 0; j < 3; j++) {
        int ti = t0 - 3 + j;
        xv[j] = (ti >= 0) ? in[(size_t)ti * HID + c] : 0.f;
    }
    #pragma unroll
    for (int j = 0; j < CT; j++)
        xv[3 + j] = in[(size_t)(t0 + j) * HID + c];

    #pragma unroll
    for (int i = 0; i < CT; i++) {
        float acc = 0.f;
        #pragma unroll
        for (int j = 0; j < 4; j++)
            acc = fmaf(xv[i + j], wc[j], acc);
        float s1 = acc / (1.f + expf(-acc));
        float s2 = s1 / (1.f + expf(-s1));
        out[(size_t)(t0 + i) * HID + c] = s2;
    }
}

// ---------------- merged l2norm(q), l2norm(k), beta ----------------
__global__ void l2beta_k(float* __restrict__ pq, float* __restrict__ pk,
                         const float* __restrict__ hbuf, const float* __restrict__ Wb,
                         float* __restrict__ beta) {
    int t = blockIdx.x;
    int y = blockIdx.y;
    int h = threadIdx.x >> 5, l = threadIdx.x & 31;
    if (y < 2) {
        float* r = (y ? pk : pq) + t * HID + h * HD;
        float a = r[l], b = r[l + 32];
        float ss = a * a + b * b;
        #pragma unroll
        for (int m = 16; m; m >>= 1) ss += __shfl_xor_sync(0xffffffffu, ss, m);
        float inv = 1.f / fmaxf(sqrtf(ss), 1e-12f);
        r[l] = a * inv;
        r[l + 32] = b * inv;
    } else {
        const float* hr = hbuf + t * HID;
        const float* wr = Wb + h * HID;
        float s = 0.f;
        for (int i = l; i < HID; i += 32) s = fmaf(hr[i], wr[i], s);
        #pragma unroll
        for (int m = 16; m; m >>= 1) s += __shfl_xor_sync(0xffffffffu, s, m);
        if (l == 0) beta[t * NH + h] = 1.f / (1.f + expf(-s));
    }
}

// ---------------- delta scan (4-chain dots + next-step prefetch) ----------------
__global__ void delta_scan_k(const float* __restrict__ kb, const float* __restrict__ qb,
                             const float* __restrict__ vb, const float* __restrict__ betab,
                             float* __restrict__ ob, float* __restrict__ Sout) {
    int gtid = blockIdx.x * blockDim.x + threadIdx.x;
    int sub  = gtid & 3;
    int task = gtid >> 2;
    int head = task >> 6;
    int row  = task & 63;
    int c0   = sub << 4;

    float S[16];
    #pragma unroll
    for (int j = 0; j < 16; j++) S[j] = 0.f;

    const float* kp = kb + head * HD + c0;
    const float* qp = qb + head * HD + c0;
    const float* vp = vb + head * HD + row;
    const float* bp = betab + head;
    float* op = ob + head * HD + row;

    float kk[16], qq[16], vt, bt;
    #pragma unroll
    for (int j = 0; j < 16; j += 4) {
        *(float4*)(kk + j) = *(const float4*)(kp + j);
        *(float4*)(qq + j) = *(const float4*)(qp + j);
    }
    vt = *vp; bt = *bp;

    for (int t = 0; t < TT; t++) {
        float nk[16], nq[16], nvt = 0.f, nbt = 0.f;
        if (t + 1 < TT) {
            const float* kp1 = kp + HID;
            const float* qp1 = qp + HID;
            #pragma unroll
            for (int j = 0; j < 16; j += 4) {
                *(float4*)(nk + j) = *(const float4*)(kp1 + j);
                *(float4*)(nq + j) = *(const float4*)(qp1 + j);
            }
            nvt = vp[HID]; nbt = bp[NH];
        }

        float a0 = 0.f, a1 = 0.f, a2 = 0.f, a3 = 0.f;
        float b0 = 0.f, b1 = 0.f, b2 = 0.f, b3 = 0.f;
        float c0s = 0.f, c1s = 0.f, c2s = 0.f, c3s = 0.f;
        #pragma unroll
        for (int j = 0; j < 4; j++) {
            a0 = fmaf(S[j], kk[j], a0);           a1 = fmaf(S[j + 4], kk[j + 4], a1);
            a2 = fmaf(S[j + 8], kk[j + 8], a2);   a3 = fmaf(S[j + 12], kk[j + 12], a3);
            b0 = fmaf(S[j], qq[j], b0);           b1 = fmaf(S[j + 4], qq[j + 4], b1);
            b2 = fmaf(S[j + 8], qq[j + 8], b2);   b3 = fmaf(S[j + 12], qq[j + 12], b3);
            c0s = fmaf(kk[j], qq[j], c0s);        c1s = fmaf(kk[j + 4], qq[j + 4], c1s);
            c2s = fmaf(kk[j + 8], qq[j + 8], c2s); c3s = fmaf(kk[j + 12], qq[j + 12], c3s);
        }
        float a = (a0 + a1) + (a2 + a3);
        float b = (b0 + b1) + (b2 + b3);
        float c = (c0s + c1s) + (c2s + c3s);

        a += __shfl_xor_sync(0xffffffffu, a, 1);
        b += __shfl_xor_sync(0xffffffffu, b, 1);
        c += __shfl_xor_sync(0xffffffffu, c, 1);
        a += __shfl_xor_sync(0xffffffffu, a, 2);
        b += __shfl_xor_sync(0xffffffffu, b, 2);
        c += __shfl_xor_sync(0xffffffffu, c, 2);

        float coef = bt * (a - vt);
        float ot = b - coef * c;
        #pragma unroll
        for (int j = 0; j < 16; j++) S[j] = fmaf(-coef, kk[j], S[j]);
        if (sub == 0) op[t * HID] = ot;

        #pragma unroll
        for (int j = 0; j < 16; j++) { kk[j] = nk[j]; qq[j] = nq[j]; }
        vt = nvt; bt = nbt;
        kp += HID; qp += HID; vp += HID; bp += NH;
    }

    #pragma unroll
    for (int j = 0; j < 16; j++)
        Sout[head * HD * HD + row * HD + c0 + j] = S[j];
}

// ---------------- launch ----------------
extern "C" void kernel_launch(void* const* d_in, const int* in_sizes, int n_in,
                              void* d_out, int out_size) {
    const float* x_in   = (const float*)d_in[0];
    const float* attn_w = (const float*)d_in[1];
    const float* Wq     = (const float*)d_in[2];
    const float* Wk     = (const float*)d_in[3];
    const float* Wv     = (const float*)d_in[4];
    const float* cq     = (const float*)d_in[5];
    const float* ck     = (const float*)d_in[6];
    const float* cv     = (const float*)d_in[7];
    const float* Wb     = (const float*)d_in[8];
    const float* out_w  = (const float*)d_in[9];
    const float* Wout   = (const float*)d_in[10];
    const float* mlp_w  = (const float*)d_in[11];
    const float* Wg     = (const float*)d_in[12];
    const float* Wu     = (const float*)d_in[13];
    const float* Wd     = (const float*)d_in[14];

    float *h, *qr, *kr, *vr, *q, *k, *v, *beta, *o, *x1, *Ssc;
    cudaGetSymbolAddress((void**)&h,   g_h);
    cudaGetSymbolAddress((void**)&qr,  g_qr);
    cudaGetSymbolAddress((void**)&kr,  g_kr);
    cudaGetSymbolAddress((void**)&vr,  g_vr);
    cudaGetSymbolAddress((void**)&q,   g_q);
    cudaGetSymbolAddress((void**)&k,   g_k);
    cudaGetSymbolAddress((void**)&v,   g_v);
    cudaGetSymbolAddress((void**)&beta,g_beta);
    cudaGetSymbolAddress((void**)&o,   g_o);
    cudaGetSymbolAddress((void**)&x1,  g_x1);
    cudaGetSymbolAddress((void**)&Ssc, g_Ssc);

    f16 *hh, *onh, *h2h, *acth, *wq, *wk, *wv, *wo, *wg, *wu, *wd;
    cudaGetSymbolAddress((void**)&hh,   g_hh);
    cudaGetSymbolAddress((void**)&onh,  g_onh);
    cudaGetSymbolAddress((void**)&h2h,  g_h2h);
    cudaGetSymbolAddress((void**)&acth, g_acth);
    cudaGetSymbolAddress((void**)&wq, g_wq); cudaGetSymbolAddress((void**)&wk, g_wk);
    cudaGetSymbolAddress((void**)&wv, g_wv); cudaGetSymbolAddress((void**)&wo, g_wo);
    cudaGetSymbolAddress((void**)&wg, g_wg); cudaGetSymbolAddress((void**)&wu, g_wu);
    cudaGetSymbolAddress((void**)&wd, g_wd);

    float* out_x = (float*)d_out;
    float* Sdst = (out_size >= TT * HID + NH * HD * HD) ? (out_x + TT * HID) : Ssc;

    cudaFuncSetAttribute(mgemm<0>, cudaFuncAttributeMaxDynamicSharedMemorySize, G_SMEM);
    cudaFuncSetAttribute(mgemm<1>, cudaFuncAttributeMaxDynamicSharedMemorySize, G_SMEM);
    cudaFuncSetAttribute(gateup_k, cudaFuncAttributeMaxDynamicSharedMemorySize, GU_SMEM);

    // ---- convert weights to fp16 (one batched pass) ----
    {
        C7 cp;
        cp.s[0] = Wq;   cp.d[0] = wq; cp.n4[0] = HID * HID / 4;
        cp.s[1] = Wk;   cp.d[1] = wk; cp.n4[1] = HID * HID / 4;
        cp.s[2] = Wv;   cp.d[2] = wv; cp.n4[2] = HID * HID / 4;
        cp.s[3] = Wout; cp.d[3] = wo; cp.n4[3] = HID * HID / 4;
        cp.s[4] = Wg;   cp.d[4] = wg; cp.n4[4] = INTER * HID / 4;
        cp.s[5] = Wu;   cp.d[5] = wu; cp.n4[5] = INTER * HID / 4;
        cp.s[6] = Wd;   cp.d[6] = wd; cp.n4[6] = HID * INTER / 4;
        dim3 g((INTER * HID / 4 + 255) / 256, 7);
        cvt7_k<<<g, 256>>>(cp);
    }

    GP z0 = {};

    // ---- attention sub-block ----
    rmsnorm_k<<<TT, 256>>>(x_in, attn_w, h, hh);

    {   // fused q/k/v projection
        GP p = z0;
        p.B[0] = wq; p.C[0] = qr;
        p.B[1] = wk; p.C[1] = kr;
        p.B[2] = wv; p.C[2] = vr;
        dim3 g(HID / 128, TT / 128, 3);
        mgemm<0><<<g, 256, G_SMEM>>>(hh, p, TT, HID, HID);
    }

    {   // sliding-window conv + double-silu for q/k/v
        CP3 cp = {{qr, kr, vr}, {cq, ck, cv}, {q, k, v}};
        dim3 g((HID / 256) * (TT / CT), 3);
        conv_sw_k<<<g, 256>>>(cp);
    }

    l2beta_k<<<dim3(TT, 3), 1024>>>(q, k, h, Wb, beta);

    delta_scan_k<<<64, 128>>>(k, q, v, beta, o, Sdst);

    rmsnorm_k<<<TT, 256>>>(o, out_w, nullptr, onh);
    {   // output projection + residual
        GP p = z0;
        p.B[0] = wo; p.C[0] = x1; p.R[0] = x_in;
        dim3 g(HID / 128, TT / 128, 1);
        mgemm<1><<<g, 256, G_SMEM>>>(onh, p, TT, HID, HID);
    }

    // ---- MLP sub-block ----
    rmsnorm_k<<<TT, 256>>>(x1, mlp_w, nullptr, h2h);
    {   // fused gate+up projection + swiglu -> acth fp16
        dim3 g(INTER / 64, TT / 128);   // (88, 8)
        gateup_k<<<g, 256, GU_SMEM>>>(h2h, wg, wu, acth, TT, INTER, HID);
    }
    {   // down projection + residual
        GP p = z0;
        p.B[0] = wd; p.C[0] = out_x; p.R[0] = x1;
        dim3 g(HID / 128, TT / 128, 1);
        mgemm<1><<<g, 256, G_SMEM>>>(acth, p, TT, HID, INTER);
    }
}

// round 15
// speedup vs baseline: 1.9987x; 1.0891x over previous
#include <cuda_runtime.h>
#include <cuda_fp16.h>
#include <math.h>
#include <stdint.h>

#define HID 2048
#define TT 1024
#define NH 32
#define HD 64
#define INTER 5632

typedef __half f16;

// ---------------- scratch (no allocations allowed) ----------------
__device__ float g_h[TT*HID];
__device__ float g_qr[TT*HID];
__device__ float g_kr[TT*HID];
__device__ float g_vr[TT*HID];
__device__ float g_q[TT*HID];
__device__ float g_k[TT*HID];
__device__ float g_v[TT*HID];
__device__ float g_beta[TT*NH];
__device__ float g_o[TT*HID];
__device__ float g_x1[TT*HID];
__device__ float g_Ssc[NH*HD*HD];

// fp16 operand buffers
__device__ f16 g_hh[TT*HID];
__device__ f16 g_onh[TT*HID];
__device__ f16 g_h2h[TT*HID];
__device__ f16 g_acth[TT*INTER];
__device__ f16 g_wq[HID*HID], g_wk[HID*HID], g_wv[HID*HID], g_wo[HID*HID];
__device__ f16 g_wg[INTER*HID], g_wu[INTER*HID], g_wd[HID*INTER];

// ================= helpers =================
__device__ __forceinline__ uint32_t smem_u32(const void* p) {
    uint32_t a;
    asm("{ .reg .u64 t; cvta.to.shared.u64 t, %1; cvt.u32.u64 %0, t; }" : "=r"(a) : "l"(p));
    return a;
}
__device__ __forceinline__ void ldmx4(uint32_t& r0, uint32_t& r1, uint32_t& r2, uint32_t& r3,
                                      uint32_t addr) {
    asm volatile("ldmatrix.sync.aligned.m8n8.x4.shared.b16 {%0,%1,%2,%3}, [%4];"
                 : "=r"(r0), "=r"(r1), "=r"(r2), "=r"(r3) : "r"(addr));
}
__device__ __forceinline__ void mma16816(float* c, const uint32_t* a, const uint32_t* b) {
    asm volatile(
        "mma.sync.aligned.m16n8k16.row.col.f32.f16.f16.f32 "
        "{%0,%1,%2,%3}, {%4,%5,%6,%7}, {%8,%9}, {%0,%1,%2,%3};"
        : "+f"(c[0]), "+f"(c[1]), "+f"(c[2]), "+f"(c[3])
        : "r"(a[0]), "r"(a[1]), "r"(a[2]), "r"(a[3]), "r"(b[0]), "r"(b[1]));
}
__device__ __forceinline__ void cpasync16(uint32_t saddr, const void* gptr) {
    asm volatile("cp.async.ca.shared.global [%0], [%1], 16;" :: "r"(saddr), "l"(gptr));
}
#define CP_COMMIT() asm volatile("cp.async.commit_group;" ::: "memory")
__device__ __forceinline__ void cp_wait(int pend) {
    if (pend <= 0)      asm volatile("cp.async.wait_group 0;" ::: "memory");
    else                asm volatile("cp.async.wait_group 1;" ::: "memory");
}

#define BK 64
#define PADW 72
#define A_TILE_B (128 * PADW * 2)      // 18432 B

// ================= fp16 tensor GEMM (128x128 tile, 3-stage, 2 CTA/SM) =================
#define G_STAGE (2 * A_TILE_B)         // A + B
#define G_SMEM (3 * G_STAGE)           // 110592 B

struct GP {
    const f16* B[3];
    float* C[3];
    const float* R[3];
};

template <int RES>
__global__ void __launch_bounds__(256, 2)
mgemm(const f16* __restrict__ A, GP p, int M, int N, int K) {
    extern __shared__ char dsm[];
    const f16* __restrict__ B = p.B[blockIdx.z];
    float* __restrict__ C = p.C[blockIdx.z];
    const float* __restrict__ Rsd = RES ? p.R[blockIdx.z] : nullptr;

    const int tid = threadIdx.x;
    const int lane = tid & 31;
    const int wid = tid >> 5;
    const int wm = wid & 1;
    const int wn = wid >> 1;
    const int row0 = blockIdx.y * 128, col0 = blockIdx.x * 128;

    const f16* At = A + (size_t)row0 * K;
    const f16* Bt = B + (size_t)col0 * K;

    int rw[4], cl[4], soff[4];
    #pragma unroll
    for (int i = 0; i < 4; i++) {
        int t = i * 256 + tid;
        rw[i] = t >> 3;
        cl[i] = (t & 7) * 8;
        soff[i] = (rw[i] * PADW + cl[i]) * 2;
    }
    const uint32_t smem_base = smem_u32(dsm);

    float acc[4][4][4];
    #pragma unroll
    for (int mt = 0; mt < 4; mt++)
        #pragma unroll
        for (int nt = 0; nt < 4; nt++)
            #pragma unroll
            for (int j = 0; j < 4; j++) acc[mt][nt][j] = 0.f;

    const int aRow = wm * 64 + (lane & 15);
    const int aCol = (lane >> 4) * 8;
    const int bRow = wn * 32 + (lane >> 4) * 8 + (lane & 7);
    const int bCol = ((lane >> 3) & 1) * 8;

    const int nchunk = K / BK;

    auto issue = [&](int c) {
        uint32_t sb = smem_base + (c % 3) * G_STAGE;
        int gco = c * BK;
        #pragma unroll
        for (int i = 0; i < 4; i++) {
            size_t go = (size_t)rw[i] * K + gco + cl[i];
            cpasync16(sb + soff[i],            At + go);
            cpasync16(sb + A_TILE_B + soff[i], Bt + go);
        }
    };

    issue(0); CP_COMMIT();
    issue(1); CP_COMMIT();

    for (int c = 0; c < nchunk; c++) {
        cp_wait(c + 1 < nchunk ? 1 : 0);
        __syncthreads();
        if (c + 2 < nchunk) { issue(c + 2); CP_COMMIT(); }

        const uint32_t sbase = smem_base + (c % 3) * G_STAGE;
        const uint32_t aH = sbase;
        const uint32_t bH = sbase + A_TILE_B;

        #pragma unroll
        for (int kt = 0; kt < 4; kt++) {
            uint32_t ah[4][4], bh[4][2];
            #pragma unroll
            for (int mt = 0; mt < 4; mt++) {
                uint32_t off = ((uint32_t)(aRow + mt * 16) * PADW + aCol + kt * 16) * 2;
                ldmx4(ah[mt][0], ah[mt][1], ah[mt][2], ah[mt][3], aH + off);
            }
            #pragma unroll
            for (int n2 = 0; n2 < 2; n2++) {
                uint32_t off = ((uint32_t)(bRow + n2 * 16) * PADW + bCol + kt * 16) * 2;
                uint32_t r0, r1, r2, r3;
                ldmx4(r0, r1, r2, r3, bH + off);
                bh[n2 * 2][0] = r0;     bh[n2 * 2][1] = r1;
                bh[n2 * 2 + 1][0] = r2; bh[n2 * 2 + 1][1] = r3;
            }
            #pragma unroll
            for (int mt = 0; mt < 4; mt++)
                #pragma unroll
                for (int nt = 0; nt < 4; nt++)
                    mma16816(acc[mt][nt], ah[mt], bh[nt]);
        }
    }

    #pragma unroll
    for (int mt = 0; mt < 4; mt++) {
        int r0g = row0 + wm * 64 + mt * 16 + (lane >> 2);
        #pragma unroll
        for (int nt = 0; nt < 4; nt++) {
            int cg = col0 + wn * 32 + nt * 8 + (lane & 3) * 2;
            float2 v0 = make_float2(acc[mt][nt][0], acc[mt][nt][1]);
            float2 v1 = make_float2(acc[mt][nt][2], acc[mt][nt][3]);
            if (RES) {
                float2 q0 = *(const float2*)(Rsd + (size_t)r0g * N + cg);
                float2 q1 = *(const float2*)(Rsd + (size_t)(r0g + 8) * N + cg);
                v0.x += q0.x; v0.y += q0.y;
                v1.x += q1.x; v1.y += q1.y;
            }
            *(float2*)(C + (size_t)r0g * N + cg) = v0;
            *(float2*)(C + (size_t)(r0g + 8) * N + cg) = v1;
        }
    }
}

// ================= fused gate+up+swiglu GEMM =================
#define B_TILE_B (64 * PADW * 2)            // 9216 B
#define GU_STAGE (A_TILE_B + 2 * B_TILE_B)  // 36864 B
#define GU_SMEM (3 * GU_STAGE)              // 110592 B

__global__ void __launch_bounds__(256, 2)
gateup_k(const f16* __restrict__ A, const f16* __restrict__ Bg,
         const f16* __restrict__ Bu, f16* __restrict__ Ch, int M, int N, int K) {
    extern __shared__ char dsm[];
    const int tid = threadIdx.x;
    const int lane = tid & 31;
    const int wid = tid >> 5;
    const int wm = wid & 1;
    const int wn = wid >> 1;
    const int row0 = blockIdx.y * 128, col0 = blockIdx.x * 64;

    const f16* At  = A  + (size_t)row0 * K;
    const f16* Bgt = Bg + (size_t)col0 * K;
    const f16* But = Bu + (size_t)col0 * K;

    int arw[4], acl[4], asoff[4];
    #pragma unroll
    for (int i = 0; i < 4; i++) {
        int t = i * 256 + tid;
        arw[i] = t >> 3;
        acl[i] = (t & 7) * 8;
        asoff[i] = (arw[i] * PADW + acl[i]) * 2;
    }
    int brw[2], bcl[2], bsoff[2];
    #pragma unroll
    for (int i = 0; i < 2; i++) {
        int t = i * 256 + tid;
        brw[i] = t >> 3;
        bcl[i] = (t & 7) * 8;
        bsoff[i] = (brw[i] * PADW + bcl[i]) * 2;
    }
    const uint32_t smem_base = smem_u32(dsm);

    float ag[4][2][4], au[4][2][4];
    #pragma unroll
    for (int mt = 0; mt < 4; mt++)
        #pragma unroll
        for (int nt = 0; nt < 2; nt++)
            #pragma unroll
            for (int j = 0; j < 4; j++) { ag[mt][nt][j] = 0.f; au[mt][nt][j] = 0.f; }

    const int aRow = wm * 64 + (lane & 15);
    const int aCol = (lane >> 4) * 8;
    const int bRow = wn * 16 + (lane >> 4) * 8 + (lane & 7);
    const int bCol = ((lane >> 3) & 1) * 8;

    const int nchunk = K / BK;

    auto issue = [&](int c) {
        uint32_t sb = smem_base + (c % 3) * GU_STAGE;
        int gco = c * BK;
        #pragma unroll
        for (int i = 0; i < 4; i++)
            cpasync16(sb + asoff[i], At + (size_t)arw[i] * K + gco + acl[i]);
        #pragma unroll
        for (int i = 0; i < 2; i++) {
            size_t go = (size_t)brw[i] * K + gco + bcl[i];
            cpasync16(sb + A_TILE_B + bsoff[i],            Bgt + go);
            cpasync16(sb + A_TILE_B + B_TILE_B + bsoff[i], But + go);
        }
    };

    issue(0); CP_COMMIT();
    issue(1); CP_COMMIT();

    for (int c = 0; c < nchunk; c++) {
        cp_wait(c + 1 < nchunk ? 1 : 0);
        __syncthreads();
        if (c + 2 < nchunk) { issue(c + 2); CP_COMMIT(); }

        const uint32_t sbase = smem_base + (c % 3) * GU_STAGE;
        const uint32_t aH = sbase;
        const uint32_t gH = sbase + A_TILE_B;
        const uint32_t uH = sbase + A_TILE_B + B_TILE_B;

        #pragma unroll
        for (int kt = 0; kt < 4; kt++) {
            uint32_t ah[4][4], bg[2][2], bu[2][2];
            #pragma unroll
            for (int mt = 0; mt < 4; mt++) {
                uint32_t off = ((uint32_t)(aRow + mt * 16) * PADW + aCol + kt * 16) * 2;
                ldmx4(ah[mt][0], ah[mt][1], ah[mt][2], ah[mt][3], aH + off);
            }
            {
                uint32_t off = ((uint32_t)bRow * PADW + bCol + kt * 16) * 2;
                uint32_t r0, r1, r2, r3;
                ldmx4(r0, r1, r2, r3, gH + off);
                bg[0][0] = r0; bg[0][1] = r1; bg[1][0] = r2; bg[1][1] = r3;
                ldmx4(r0, r1, r2, r3, uH + off);
                bu[0][0] = r0; bu[0][1] = r1; bu[1][0] = r2; bu[1][1] = r3;
            }
            #pragma unroll
            for (int mt = 0; mt < 4; mt++)
                #pragma unroll
                for (int nt = 0; nt < 2; nt++) {
                    mma16816(ag[mt][nt], ah[mt], bg[nt]);
                    mma16816(au[mt][nt], ah[mt], bu[nt]);
                }
        }
    }

    #pragma unroll
    for (int mt = 0; mt < 4; mt++) {
        int r0g = row0 + wm * 64 + mt * 16 + (lane >> 2);
        #pragma unroll
        for (int nt = 0; nt < 2; nt++) {
            int cg = col0 + wn * 16 + nt * 8 + (lane & 3) * 2;
            #pragma unroll
            for (int half = 0; half < 2; half++) {
                int rr2 = r0g + half * 8;
                size_t idx = (size_t)rr2 * N + cg;
                float g0 = ag[mt][nt][half * 2], g1 = ag[mt][nt][half * 2 + 1];
                float u0 = au[mt][nt][half * 2], u1 = au[mt][nt][half * 2 + 1];
                float y0 = (g0 / (1.f + expf(-g0))) * u0;
                float y1 = (g1 / (1.f + expf(-g1))) * u1;
                __half2 hv = __floats2half2_rn(y0, y1);
                *(__half2*)(Ch + idx) = hv;
            }
        }
    }
}

// ---------------- batched fp32 -> fp16 weight converter ----------------
struct C7 {
    const float* s[7];
    f16* d[7];
    int n4[7];
};
__global__ void cvt7_k(C7 p) {
    int z = blockIdx.y;
    int i4 = blockIdx.x * 256 + threadIdx.x;
    if (i4 >= p.n4[z]) return;
    float4 v = ((const float4*)p.s[z])[i4];
    __half2 h0 = __floats2half2_rn(v.x, v.y);
    __half2 h1 = __floats2half2_rn(v.z, v.w);
    ((uint2*)p.d[z])[i4] = make_uint2(*(uint32_t*)&h0, *(uint32_t*)&h1);
}

// ---------------- RMSNorm (fp32 optional + fp16 out) ----------------
__global__ void rmsnorm_k(const float* __restrict__ x, const float* __restrict__ w,
                          float* __restrict__ out, f16* __restrict__ oh) {
    int row = blockIdx.x;
    const float* xr = x + row * HID;
    float ss = 0.f;
    for (int i = threadIdx.x; i < HID; i += 256) { float v = xr[i]; ss += v * v; }
    #pragma unroll
    for (int m = 16; m; m >>= 1) ss += __shfl_xor_sync(0xffffffffu, ss, m);
    __shared__ float red[8];
    if ((threadIdx.x & 31) == 0) red[threadIdx.x >> 5] = ss;
    __syncthreads();
    if (threadIdx.x < 8) {
        float r = red[threadIdx.x];
        #pragma unroll
        for (int m = 4; m; m >>= 1) r += __shfl_xor_sync(0xffu, r, m);
        if (threadIdx.x == 0) red[0] = r;
    }
    __syncthreads();
    float scale = rsqrtf(red[0] * (1.0f / (float)HID) + 1e-6f);
    for (int i = threadIdx.x; i < HID; i += 256) {
        float y = xr[i] * scale * w[i];
        if (out) out[row * HID + i] = y;
        oh[row * HID + i] = __float2half_rn(y);
    }
}

// ---------------- sliding-window causal dwconv (K=4) + silu(silu(.)) ----------------
#define CT 8
struct CP3 { const float* in[3]; const float* w[3]; float* out[3]; };

__global__ void conv_sw_k(CP3 p) {
    int z = blockIdx.y;
    const float* __restrict__ in = p.in[z];
    float* __restrict__ out = p.out[z];

    int bx = blockIdx.x;
    int c  = (bx & 7) * 256 + threadIdx.x;
    int t0 = (bx >> 3) * CT;

    float4 wv = *(const float4*)(p.w[z] + c * 4);
    float wc[4] = {wv.x, wv.y, wv.z, wv.w};

    float xv[CT + 3];
    #pragma unroll
    for (int j = 0; j < 3; j++) {
        int ti = t0 - 3 + j;
        xv[j] = (ti >= 0) ? in[(size_t)ti * HID + c] : 0.f;
    }
    #pragma unroll
    for (int j = 0; j < CT; j++)
        xv[3 + j] = in[(size_t)(t0 + j) * HID + c];

    #pragma unroll
    for (int i = 0; i < CT; i++) {
        float acc = 0.f;
        #pragma unroll
        for (int j = 0; j < 4; j++)
            acc = fmaf(xv[i + j], wc[j], acc);
        float s1 = acc / (1.f + expf(-acc));
        float s2 = s1 / (1.f + expf(-s1));
        out[(size_t)(t0 + i) * HID + c] = s2;
    }
}

// ---------------- merged l2norm(q), l2norm(k), beta ----------------
__global__ void l2beta_k(float* __restrict__ pq, float* __restrict__ pk,
                         const float* __restrict__ hbuf, const float* __restrict__ Wb,
                         float* __restrict__ beta) {
    int t = blockIdx.x;
    int y = blockIdx.y;
    int h = threadIdx.x >> 5, l = threadIdx.x & 31;
    if (y < 2) {
        float* r = (y ? pk : pq) + t * HID + h * HD;
        float a = r[l], b = r[l + 32];
        float ss = a * a + b * b;
        #pragma unroll
        for (int m = 16; m; m >>= 1) ss += __shfl_xor_sync(0xffffffffu, ss, m);
        float inv = 1.f / fmaxf(sqrtf(ss), 1e-12f);
        r[l] = a * inv;
        r[l + 32] = b * inv;
    } else {
        const float* hr = hbuf + t * HID;
        const float* wr = Wb + h * HID;
        float s = 0.f;
        for (int i = l; i < HID; i += 32) s = fmaf(hr[i], wr[i], s);
        #pragma unroll
        for (int m = 16; m; m >>= 1) s += __shfl_xor_sync(0xffffffffu, s, m);
        if (l == 0) beta[t * NH + h] = 1.f / (1.f + expf(-s));
    }
}

// ---------------- delta scan: one CTA per head, smem-staged chunks ----------------
// 256 threads = 64 row-tasks x 4 lanes. k/q/v/beta staged in double-buffered smem
// 16 timesteps at a time; global traffic per head drops 64x vs per-task loads.
#define SCH 16
__global__ void __launch_bounds__(256)
delta_scan_k(const float* __restrict__ kb, const float* __restrict__ qb,
             const float* __restrict__ vb, const float* __restrict__ betab,
             float* __restrict__ ob, float* __restrict__ Sout) {
    __shared__ float sk[2][SCH][64];
    __shared__ float sq[2][SCH][64];
    __shared__ float sv[2][SCH][64];
    __shared__ float sb[2][SCH];

    const int head = blockIdx.x;
    const int tid = threadIdx.x;
    const int r   = tid >> 2;
    const int sub = tid & 3;
    const int c0  = sub << 4;

    const float* kB = kb + head * HD;
    const float* qB = qb + head * HD;
    const float* vB = vb + head * HD;
    const float* bB = betab + head;
    float* oB = ob + head * HD;

    const int lt = tid >> 4;          // 0..15 (timestep slot)
    const int lc = (tid & 15) << 2;   // 0..60 (col, float4)

    float S[16];
    #pragma unroll
    for (int j = 0; j < 16; j++) S[j] = 0.f;

    // load chunk 0 into buf 0
    float4 pk, pq, pv;
    float pb = 0.f;
    {
        size_t base = (size_t)lt * HID + lc;
        pk = *(const float4*)(kB + base);
        pq = *(const float4*)(qB + base);
        pv = *(const float4*)(vB + base);
        if (tid < SCH) pb = bB[(size_t)tid * NH];
        *(float4*)&sk[0][lt][lc] = pk;
        *(float4*)&sq[0][lt][lc] = pq;
        *(float4*)&sv[0][lt][lc] = pv;
        if (tid < SCH) sb[0][tid] = pb;
    }

    const int NCH = TT / SCH;   // 64
    for (int ch = 0; ch < NCH; ch++) {
        __syncthreads();
        const int buf = ch & 1;

        // prefetch next chunk from global (hidden behind 16 steps of compute)
        if (ch + 1 < NCH) {
            size_t base = (size_t)((ch + 1) * SCH + lt) * HID + lc;
            pk = *(const float4*)(kB + base);
            pq = *(const float4*)(qB + base);
            pv = *(const float4*)(vB + base);
            if (tid < SCH) pb = bB[(size_t)((ch + 1) * SCH + tid) * NH];
        }

        // preload step 0 operands from smem
        float kk[16], qq[16];
        #pragma unroll
        for (int j = 0; j < 16; j += 4) {
            *(float4*)(kk + j) = *(const float4*)&sk[buf][0][c0 + j];
            *(float4*)(qq + j) = *(const float4*)&sq[buf][0][c0 + j];
        }

        #pragma unroll
        for (int i = 0; i < SCH; i++) {
            float vt = sv[buf][i][r];
            float bt = sb[buf][i];

            float nk[16], nq[16];
            if (i + 1 < SCH) {
                #pragma unroll
                for (int j = 0; j < 16; j += 4) {
                    *(float4*)(nk + j) = *(const float4*)&sk[buf][i + 1][c0 + j];
                    *(float4*)(nq + j) = *(const float4*)&sq[buf][i + 1][c0 + j];
                }
            }

            float a0 = 0.f, a1 = 0.f, a2 = 0.f, a3 = 0.f;
            float b0 = 0.f, b1 = 0.f, b2 = 0.f, b3 = 0.f;
            float c0s = 0.f, c1s = 0.f, c2s = 0.f, c3s = 0.f;
            #pragma unroll
            for (int j = 0; j < 4; j++) {
                a0 = fmaf(S[j], kk[j], a0);           a1 = fmaf(S[j + 4], kk[j + 4], a1);
                a2 = fmaf(S[j + 8], kk[j + 8], a2);   a3 = fmaf(S[j + 12], kk[j + 12], a3);
                b0 = fmaf(S[j], qq[j], b0);           b1 = fmaf(S[j + 4], qq[j + 4], b1);
                b2 = fmaf(S[j + 8], qq[j + 8], b2);   b3 = fmaf(S[j + 12], qq[j + 12], b3);
                c0s = fmaf(kk[j], qq[j], c0s);        c1s = fmaf(kk[j + 4], qq[j + 4], c1s);
                c2s = fmaf(kk[j + 8], qq[j + 8], c2s); c3s = fmaf(kk[j + 12], qq[j + 12], c3s);
            }
            float a = (a0 + a1) + (a2 + a3);
            float b = (b0 + b1) + (b2 + b3);
            float c = (c0s + c1s) + (c2s + c3s);

            a += __shfl_xor_sync(0xffffffffu, a, 1);
            b += __shfl_xor_sync(0xffffffffu, b, 1);
            c += __shfl_xor_sync(0xffffffffu, c, 1);
            a += __shfl_xor_sync(0xffffffffu, a, 2);
            b += __shfl_xor_sync(0xffffffffu, b, 2);
            c += __shfl_xor_sync(0xffffffffu, c, 2);

            float coef = bt * (a - vt);
            float ot = b - coef * c;
            #pragma unroll
            for (int j = 0; j < 16; j++) S[j] = fmaf(-coef, kk[j], S[j]);
            if (sub == 0) oB[(size_t)(ch * SCH + i) * HID + r] = ot;

            if (i + 1 < SCH) {
                #pragma unroll
                for (int j = 0; j < 16; j++) { kk[j] = nk[j]; qq[j] = nq[j]; }
            }
        }

        // store prefetched chunk into the other buffer (safe: top-of-loop sync
        // guarantees everyone finished reading it two chunks ago)
        if (ch + 1 < NCH) {
            const int nb = buf ^ 1;
            *(float4*)&sk[nb][lt][lc] = pk;
            *(float4*)&sq[nb][lt][lc] = pq;
            *(float4*)&sv[nb][lt][lc] = pv;
            if (tid < SCH) sb[nb][tid] = pb;
        }
    }

    #pragma unroll
    for (int j = 0; j < 16; j++)
        Sout[head * HD * HD + r * HD + c0 + j] = S[j];
}

// ---------------- launch ----------------
extern "C" void kernel_launch(void* const* d_in, const int* in_sizes, int n_in,
                              void* d_out, int out_size) {
    const float* x_in   = (const float*)d_in[0];
    const float* attn_w = (const float*)d_in[1];
    const float* Wq     = (const float*)d_in[2];
    const float* Wk     = (const float*)d_in[3];
    const float* Wv     = (const float*)d_in[4];
    const float* cq     = (const float*)d_in[5];
    const float* ck     = (const float*)d_in[6];
    const float* cv     = (const float*)d_in[7];
    const float* Wb     = (const float*)d_in[8];
    const float* out_w  = (const float*)d_in[9];
    const float* Wout   = (const float*)d_in[10];
    const float* mlp_w  = (const float*)d_in[11];
    const float* Wg     = (const float*)d_in[12];
    const float* Wu     = (const float*)d_in[13];
    const float* Wd     = (const float*)d_in[14];

    float *h, *qr, *kr, *vr, *q, *k, *v, *beta, *o, *x1, *Ssc;
    cudaGetSymbolAddress((void**)&h,   g_h);
    cudaGetSymbolAddress((void**)&qr,  g_qr);
    cudaGetSymbolAddress((void**)&kr,  g_kr);
    cudaGetSymbolAddress((void**)&vr,  g_vr);
    cudaGetSymbolAddress((void**)&q,   g_q);
    cudaGetSymbolAddress((void**)&k,   g_k);
    cudaGetSymbolAddress((void**)&v,   g_v);
    cudaGetSymbolAddress((void**)&beta,g_beta);
    cudaGetSymbolAddress((void**)&o,   g_o);
    cudaGetSymbolAddress((void**)&x1,  g_x1);
    cudaGetSymbolAddress((void**)&Ssc, g_Ssc);

    f16 *hh, *onh, *h2h, *acth, *wq, *wk, *wv, *wo, *wg, *wu, *wd;
    cudaGetSymbolAddress((void**)&hh,   g_hh);
    cudaGetSymbolAddress((void**)&onh,  g_onh);
    cudaGetSymbolAddress((void**)&h2h,  g_h2h);
    cudaGetSymbolAddress((void**)&acth, g_acth);
    cudaGetSymbolAddress((void**)&wq, g_wq); cudaGetSymbolAddress((void**)&wk, g_wk);
    cudaGetSymbolAddress((void**)&wv, g_wv); cudaGetSymbolAddress((void**)&wo, g_wo);
    cudaGetSymbolAddress((void**)&wg, g_wg); cudaGetSymbolAddress((void**)&wu, g_wu);
    cudaGetSymbolAddress((void**)&wd, g_wd);

    float* out_x = (float*)d_out;
    float* Sdst = (out_size >= TT * HID + NH * HD * HD) ? (out_x + TT * HID) : Ssc;

    cudaFuncSetAttribute(mgemm<0>, cudaFuncAttributeMaxDynamicSharedMemorySize, G_SMEM);
    cudaFuncSetAttribute(mgemm<1>, cudaFuncAttributeMaxDynamicSharedMemorySize, G_SMEM);
    cudaFuncSetAttribute(gateup_k, cudaFuncAttributeMaxDynamicSharedMemorySize, GU_SMEM);

    // ---- convert weights to fp16 (one batched pass) ----
    {
        C7 cp;
        cp.s[0] = Wq;   cp.d[0] = wq; cp.n4[0] = HID * HID / 4;
        cp.s[1] = Wk;   cp.d[1] = wk; cp.n4[1] = HID * HID / 4;
        cp.s[2] = Wv;   cp.d[2] = wv; cp.n4[2] = HID * HID / 4;
        cp.s[3] = Wout; cp.d[3] = wo; cp.n4[3] = HID * HID / 4;
        cp.s[4] = Wg;   cp.d[4] = wg; cp.n4[4] = INTER * HID / 4;
        cp.s[5] = Wu;   cp.d[5] = wu; cp.n4[5] = INTER * HID / 4;
        cp.s[6] = Wd;   cp.d[6] = wd; cp.n4[6] = HID * INTER / 4;
        dim3 g((INTER * HID / 4 + 255) / 256, 7);
        cvt7_k<<<g, 256>>>(cp);
    }

    GP z0 = {};

    // ---- attention sub-block ----
    rmsnorm_k<<<TT, 256>>>(x_in, attn_w, h, hh);

    {   // fused q/k/v projection
        GP p = z0;
        p.B[0] = wq; p.C[0] = qr;
        p.B[1] = wk; p.C[1] = kr;
        p.B[2] = wv; p.C[2] = vr;
        dim3 g(HID / 128, TT / 128, 3);
        mgemm<0><<<g, 256, G_SMEM>>>(hh, p, TT, HID, HID);
    }

    {   // sliding-window conv + double-silu for q/k/v
        CP3 cp = {{qr, kr, vr}, {cq, ck, cv}, {q, k, v}};
        dim3 g((HID / 256) * (TT / CT), 3);
        conv_sw_k<<<g, 256>>>(cp);
    }

    l2beta_k<<<dim3(TT, 3), 1024>>>(q, k, h, Wb, beta);

    delta_scan_k<<<NH, 256>>>(k, q, v, beta, o, Sdst);

    rmsnorm_k<<<TT, 256>>>(o, out_w, nullptr, onh);
    {   // output projection + residual
        GP p = z0;
        p.B[0] = wo; p.C[0] = x1; p.R[0] = x_in;
        dim3 g(HID / 128, TT / 128, 1);
        mgemm<1><<<g, 256, G_SMEM>>>(onh, p, TT, HID, HID);
    }

    // ---- MLP sub-block ----
    rmsnorm_k<<<TT, 256>>>(x1, mlp_w, nullptr, h2h);
    {   // fused gate+up projection + swiglu -> acth fp16
        dim3 g(INTER / 64, TT / 128);   // (88, 8)
        gateup_k<<<g, 256, GU_SMEM>>>(h2h, wg, wu, acth, TT, INTER, HID);
    }
    {   // down projection + residual
        GP p = z0;
        p.B[0] = wd; p.C[0] = out_x; p.R[0] = x1;
        dim3 g(HID / 128, TT / 128, 1);
        mgemm<1><<<g, 256, G_SMEM>>>(acth, p, TT, HID, INTER);
    }
}